// round 5
// baseline (speedup 1.0000x reference)
#include <cuda_runtime.h>
#include <cuda_bf16.h>
#include <stdint.h>

#define NB   512
#define NL   64
#define NH   128
#define NENT 200000
#define NREL 500

// ---------------- scratch (__device__ globals; no allocs allowed) ----------
__device__ float g_Rproj[NREL * NH];        // relation_emb @ in_W[128:256]
__device__ float g_vdW[NH];                 // delta_W @ in_W[256:384]
__device__ float g_vdb[NH];                 // delta_b @ in_W[256:384]
__device__ __nv_bfloat16 g_Ph[NB * NH];     // (q+ctx)*rel, bf16 hi
__device__ __nv_bfloat16 g_Pl[NB * NH];     // bf16 lo
__device__ __nv_bfloat16 g_Eh[(size_t)NENT * NH];  // entity_emb hi
__device__ __nv_bfloat16 g_El[(size_t)NENT * NH];  // entity_emb lo

// ---------------- convert entity table to split bf16 -----------------------
__global__ void convertE_kernel(const float* __restrict__ E) {
    int i = blockIdx.x * blockDim.x + threadIdx.x;      // one float4
    float4 v = ((const float4*)E)[i];
    __nv_bfloat16 h0 = __float2bfloat16(v.x);
    __nv_bfloat16 h1 = __float2bfloat16(v.y);
    __nv_bfloat16 h2 = __float2bfloat16(v.z);
    __nv_bfloat16 h3 = __float2bfloat16(v.w);
    __nv_bfloat16 l0 = __float2bfloat16(v.x - __bfloat162float(h0));
    __nv_bfloat16 l1 = __float2bfloat16(v.y - __bfloat162float(h1));
    __nv_bfloat16 l2 = __float2bfloat16(v.z - __bfloat162float(h2));
    __nv_bfloat16 l3 = __float2bfloat16(v.w - __bfloat162float(h3));
    ((__nv_bfloat162*)g_Eh)[2*i+0] = __halves2bfloat162(h0, h1);
    ((__nv_bfloat162*)g_Eh)[2*i+1] = __halves2bfloat162(h2, h3);
    ((__nv_bfloat162*)g_El)[2*i+0] = __halves2bfloat162(l0, l1);
    ((__nv_bfloat162*)g_El)[2*i+1] = __halves2bfloat162(l2, l3);
}

// ---------------- prep: fold relation/delta projections --------------------
__global__ void prep_kernel(const float* __restrict__ relation_emb,
                            const float* __restrict__ in_W,
                            const float* __restrict__ delta_W,
                            const float* __restrict__ delta_b) {
    int r = blockIdx.x, j = threadIdx.x;
    if (r < NREL) {
        __shared__ float sr[NH];
        sr[j] = relation_emb[r * NH + j];
        __syncthreads();
        float acc = 0.f;
        #pragma unroll 8
        for (int i = 0; i < NH; i++) acc += sr[i] * in_W[(NH + i) * NH + j];
        g_Rproj[r * NH + j] = acc;
    } else if (r == NREL) {
        float acc = 0.f;
        #pragma unroll 8
        for (int t = 0; t < 128; t++) acc += delta_W[t] * in_W[(256 + t) * NH + j];
        g_vdW[j] = acc;
    } else {
        float acc = 0.f;
        #pragma unroll 8
        for (int t = 0; t < 128; t++) acc += delta_b[t] * in_W[(256 + t) * NH + j];
        g_vdb[j] = acc;
    }
}

// ---------------- front: one CTA per batch row ------------------------------
#define FRONT_SMEM (19968 * 4)
__global__ __launch_bounds__(256) void front_kernel(
    const int* __restrict__ heads, const int* __restrict__ relations,
    const int* __restrict__ times, const int* __restrict__ hist_ent,
    const int* __restrict__ hist_rel, const float* __restrict__ hist_delta,
    const float* __restrict__ hist_mask, const float* __restrict__ entity_emb,
    const float* __restrict__ relation_emb, const float* __restrict__ time_emb,
    const float* __restrict__ query_W, const float* __restrict__ query_b,
    const float* __restrict__ in_W, const float* __restrict__ in_b,
    const float* __restrict__ a_W, const float* __restrict__ a_b,
    const float* __restrict__ hyper_in_W, const float* __restrict__ hyper_in_b,
    const float* __restrict__ hyper_gate_W, const float* __restrict__ hyper_gate_b,
    const float* __restrict__ attn_W, const float* __restrict__ attn_b)
{
    extern __shared__ float sm[];
    float* s_NE   = sm;
    float* s_X    = sm + 8192;
    float* s_W    = sm + 16384;
    float* s_misc = sm + 18432;
    float* s_rel    = s_misc;
    float* s_q      = s_misc + 128;
    float* s_cgate  = s_misc + 256;
    float* s_bias   = s_misc + 384;
    float* s_vdW    = s_misc + 512;
    float* s_attnW  = s_misc + 640;
    float* s_head   = s_misc + 896;
    float* s_tf     = s_misc + 1024;
    float* s_scores = s_misc + 1152;
    float* s_attn   = s_misc + 1216;
    float* s_delta  = s_misc + 1280;
    float* s_mask   = s_misc + 1344;
    int*   s_hr     = (int*)(s_misc + 1408);
    float* s_qdot   = s_misc + 1472;
    float* s_A = s_NE;

    int b = blockIdx.x, tid = threadIdx.x;

    if (tid < 128) {
        s_head[tid] = entity_emb[(size_t)heads[b] * NH + tid];
        s_rel[tid]  = relation_emb[relations[b] * NH + tid];
        s_tf[tid]   = time_emb[times[b] * NH + tid];
        s_vdW[tid]  = g_vdW[tid];
    } else {
        int j = tid - 128;
        s_attnW[j]       = attn_W[j];
        s_attnW[128 + j] = attn_W[128 + j];
    }
    if (tid < 64) {
        s_delta[tid] = hist_delta[b * NL + tid];
        s_mask[tid]  = hist_mask[b * NL + tid];
        s_hr[tid]    = hist_rel[b * NL + tid];
    }
    __syncthreads();

    if (tid < 128) {
        int j = tid;
        float acc = query_b[j];
        #pragma unroll 4
        for (int i = 0; i < 128; i++) acc += s_head[i] * query_W[i * NH + j];
        #pragma unroll 4
        for (int i = 0; i < 128; i++) acc += s_rel[i] * query_W[(128 + i) * NH + j];
        #pragma unroll 4
        for (int i = 0; i < 128; i++) acc += s_tf[i] * query_W[(256 + i) * NH + j];
        s_q[j] = acc;
    } else {
        int j = tid - 128;
        float ci = hyper_in_b[j], cg = hyper_gate_b[j];
        #pragma unroll 4
        for (int i = 0; i < 128; i++) {
            float r = s_rel[i];
            ci += r * hyper_in_W[i * NH + j];
            cg += r * hyper_gate_W[i * NH + j];
        }
        s_cgate[j] = 1.f / (1.f + __expf(-cg));
        s_bias[j]  = in_b[j] + ci + g_vdb[j];
    }
    __syncthreads();

    {
        int w = tid >> 5, lane = tid & 31;
        for (int l = w; l < NL; l += 8) {
            size_t e = (size_t)hist_ent[b * NL + l];
            ((float4*)(s_NE + l * NH))[lane] = ((const float4*)(entity_emb + e * NH))[lane];
        }
    }
    __syncthreads();

    int cgi = tid & 15, rgi = tid >> 4;
    int c0 = cgi * 8, r0 = rgi * 4;
    int wr = tid >> 4, wc = (tid & 15) * 8;
    float acc[4][8];
    float4 pw0, pw1;

    #pragma unroll
    for (int i = 0; i < 4; i++) {
        int l = r0 + i;
        float dl = s_delta[l];
        const float* rp = g_Rproj + s_hr[l] * NH + c0;
        #pragma unroll
        for (int j = 0; j < 8; j++)
            acc[i][j] = s_bias[c0 + j] + dl * s_vdW[c0 + j] + rp[j];
    }
    {
        const float4* s = (const float4*)(in_W + wr * NH + wc);
        pw0 = s[0]; pw1 = s[1];
    }
    for (int kt = 0; kt < 8; kt++) {
        __syncthreads();
        { float4* d = (float4*)(s_W + wr * NH + wc); d[0] = pw0; d[1] = pw1; }
        __syncthreads();
        if (kt < 7) {
            const float4* s = (const float4*)(in_W + ((kt + 1) * 16 + wr) * NH + wc);
            pw0 = s[0]; pw1 = s[1];
        }
        #pragma unroll
        for (int k = 0; k < 16; k++) {
            int kk = kt * 16 + k;
            float a0 = s_NE[(r0 + 0) * NH + kk];
            float a1 = s_NE[(r0 + 1) * NH + kk];
            float a2 = s_NE[(r0 + 2) * NH + kk];
            float a3 = s_NE[(r0 + 3) * NH + kk];
            float4 b0 = *(const float4*)(s_W + k * NH + c0);
            float4 b1 = *(const float4*)(s_W + k * NH + c0 + 4);
            float bb[8] = {b0.x, b0.y, b0.z, b0.w, b1.x, b1.y, b1.z, b1.w};
            #pragma unroll
            for (int j = 0; j < 8; j++) {
                acc[0][j] += a0 * bb[j]; acc[1][j] += a1 * bb[j];
                acc[2][j] += a2 * bb[j]; acc[3][j] += a3 * bb[j];
            }
        }
    }
    __syncthreads();
    #pragma unroll
    for (int i = 0; i < 4; i++)
        #pragma unroll
        for (int j = 0; j < 8; j++)
            s_X[(r0 + i) * NH + c0 + j] = acc[i][j];
    __syncthreads();

    #pragma unroll
    for (int i = 0; i < 4; i++)
        #pragma unroll
        for (int j = 0; j < 8; j++)
            acc[i][j] = a_b[c0 + j];
    {
        const float4* s = (const float4*)(a_W + wr * NH + wc);
        pw0 = s[0]; pw1 = s[1];
    }
    for (int kt = 0; kt < 8; kt++) {
        __syncthreads();
        { float4* d = (float4*)(s_W + wr * NH + wc); d[0] = pw0; d[1] = pw1; }
        __syncthreads();
        if (kt < 7) {
            const float4* s = (const float4*)(a_W + ((kt + 1) * 16 + wr) * NH + wc);
            pw0 = s[0]; pw1 = s[1];
        }
        #pragma unroll
        for (int k = 0; k < 16; k++) {
            int kk = kt * 16 + k;
            float a0 = s_X[(r0 + 0) * NH + kk];
            float a1 = s_X[(r0 + 1) * NH + kk];
            float a2 = s_X[(r0 + 2) * NH + kk];
            float a3 = s_X[(r0 + 3) * NH + kk];
            float4 b0 = *(const float4*)(s_W + k * NH + c0);
            float4 b1 = *(const float4*)(s_W + k * NH + c0 + 4);
            float bb[8] = {b0.x, b0.y, b0.z, b0.w, b1.x, b1.y, b1.z, b1.w};
            #pragma unroll
            for (int j = 0; j < 8; j++) {
                acc[0][j] += a0 * bb[j]; acc[1][j] += a1 * bb[j];
                acc[2][j] += a2 * bb[j]; acc[3][j] += a3 * bb[j];
            }
        }
    }
    __syncthreads();
    #pragma unroll
    for (int i = 0; i < 4; i++)
        #pragma unroll
        for (int j = 0; j < 8; j++)
            s_A[(r0 + i) * NH + c0 + j] = 1.f / (1.f + __expf(-acc[i][j]));
    __syncthreads();

    if (tid < 128) {
        float h = 0.f, cgt = s_cgate[tid];
        for (int l = 0; l < NL; l++) {
            float x = s_X[l * NH + tid];
            float a = s_A[l * NH + tid];
            float m = s_mask[l];
            float hn = a * h + (1.f - a) * x;
            h = m * hn + (1.f - m) * h;
            s_X[l * NH + tid] = h * cgt;
        }
    }
    __syncthreads();

    if (tid < 32) {
        float p = 0.f;
        for (int j = tid; j < 128; j += 32) p += s_q[j] * s_attnW[128 + j];
        #pragma unroll
        for (int o = 16; o; o >>= 1) p += __shfl_xor_sync(~0u, p, o);
        if (tid == 0) s_qdot[0] = p + attn_b[0];
    }
    __syncthreads();
    {
        int w = tid >> 5, lane = tid & 31;
        for (int l = w; l < NL; l += 8) {
            float p = 0.f;
            #pragma unroll
            for (int j = lane; j < 128; j += 32) p += s_X[l * NH + j] * s_attnW[j];
            #pragma unroll
            for (int o = 16; o; o >>= 1) p += __shfl_xor_sync(~0u, p, o);
            if (lane == 0) {
                float sc = tanhf(p + s_qdot[0]);
                s_scores[l] = (s_mask[l] <= 0.f) ? -1e9f : sc;
            }
        }
    }
    __syncthreads();
    if (tid < 32) {
        float v0 = s_scores[tid], v1 = s_scores[tid + 32];
        float mx = fmaxf(v0, v1);
        #pragma unroll
        for (int o = 16; o; o >>= 1) mx = fmaxf(mx, __shfl_xor_sync(~0u, mx, o));
        float e0 = __expf(v0 - mx) * s_mask[tid];
        float e1 = __expf(v1 - mx) * s_mask[tid + 32];
        float s = e0 + e1;
        #pragma unroll
        for (int o = 16; o; o >>= 1) s += __shfl_xor_sync(~0u, s, o);
        s = fmaxf(s, 1e-9f);
        s_attn[tid] = e0 / s;
        s_attn[tid + 32] = e1 / s;
    }
    __syncthreads();
    if (tid < 128) {
        float c = 0.f;
        #pragma unroll 4
        for (int l = 0; l < NL; l++) c += s_X[l * NH + tid] * s_attn[l];
        float P = (s_q[tid] + c) * s_rel[tid];
        __nv_bfloat16 hi = __float2bfloat16(P);
        float lo = P - __bfloat162float(hi);
        g_Ph[b * NH + tid] = hi;
        g_Pl[b * NH + tid] = __float2bfloat16(lo);
    }
}

// ---------------- score: persistent split-bf16 mma.sync GEMM ---------------
// 148 persistent CTAs, 512 threads. CTA: m-tile 128 (bid&3), loops n-tiles of 256.
// A (Ph/Pl full K=128) resident in smem; B (Eh/El) double-buffered via cp.async.
#define ALD 136                 // A smem row stride (bf16), 272B
#define SLD 72                  // B smem row stride per k-chunk (bf16), 144B
#define SA_H 0
#define SA_L 34816
#define SB   69632
#define BSTAGE 73728            // per stage: BH 36864 + BL 36864
#define SCORE_SMEM (SB + 2 * BSTAGE)    // 217088
#define NTILES ((NENT + 255) / 256)     // 782

#define MMA_BF16(d, a, b) asm volatile( \
    "mma.sync.aligned.m16n8k16.row.col.f32.bf16.bf16.f32 " \
    "{%0,%1,%2,%3},{%4,%5,%6,%7},{%8,%9},{%0,%1,%2,%3};" \
    : "+f"(d[0]), "+f"(d[1]), "+f"(d[2]), "+f"(d[3]) \
    : "r"(a[0]), "r"(a[1]), "r"(a[2]), "r"(a[3]), "r"(b[0]), "r"(b[1]))

#define LDSM_X4(r, addr) asm volatile( \
    "ldmatrix.sync.aligned.m8n8.x4.shared.b16 {%0,%1,%2,%3}, [%4];" \
    : "=r"((r)[0]), "=r"((r)[1]), "=r"((r)[2]), "=r"((r)[3]) : "r"(addr))

#define CP_ASYNC16(dst, src, srcsz) asm volatile( \
    "cp.async.cg.shared.global [%0], [%1], 16, %2;" \
    :: "r"(dst), "l"(src), "r"(srcsz) : "memory")

__device__ __forceinline__ uint32_t smem_u32(const void* p) {
    return (uint32_t)__cvta_generic_to_shared(p);
}

__global__ __launch_bounds__(512, 1) void score_kernel(float* __restrict__ out) {
    extern __shared__ char smem[];
    uint32_t sbase = smem_u32(smem);
    int tid = threadIdx.x, warp = tid >> 5, lane = tid & 31;
    int m0 = (blockIdx.x & 3) * 128;
    int nstart = blockIdx.x >> 2;                 // 0..36
    const int nstride = 37;

    int wm = (warp >> 3) * 64;                    // 2 warps in m
    int wn = (warp & 7) * 32;                     // 8 warps in n
    int aRow = lane & 15, aCol = (lane >> 4) * 8; // ldmatrix A
    int bRow = ((lane >> 4) << 3) + (lane & 7);   // ldmatrix B
    int bCol = ((lane >> 3) & 1) * 8;
    int arow = lane >> 2, acol = (lane & 3) * 2;  // accum layout

    // ---- A resident fill: 128 rows x 128 bf16, hi & lo ----
    #pragma unroll
    for (int i = 0; i < 4; i++) {
        int idx = tid + i * 512;                  // 0..2047
        int r = idx >> 4, c = (idx & 15) * 8;
        *(uint4*)(smem + SA_H + r * (ALD * 2) + c * 2) =
            *(const uint4*)(g_Ph + (size_t)(m0 + r) * NH + c);
        *(uint4*)(smem + SA_L + r * (ALD * 2) + c * 2) =
            *(const uint4*)(g_Pl + (size_t)(m0 + r) * NH + c);
    }

    // step s -> tile (nstart + (s>>1)*nstride), k-chunk (s&1)
    int ntiles = 0;
    for (int t = nstart; t < NTILES; t += nstride) ntiles++;
    int steps = ntiles * 2;
    if (steps == 0) return;

    // B fill for step s into stage buffer
    auto fillB = [&](int s) {
        int stage = s & 1;
        int n0 = (nstart + (s >> 1) * nstride) * 256;
        int kc = (s & 1) * 64;
        uint32_t bh = sbase + SB + stage * BSTAGE;
        uint32_t bl = bh + 36864;
        #pragma unroll
        for (int i = 0; i < 4; i++) {
            int idx = tid + i * 512;              // 0..2047
            int r = idx >> 3;                     // 0..255
            int c = (idx & 7) * 8;                // 0..56
            int er = n0 + r;
            uint32_t srcsz = (er < NENT) ? 16u : 0u;
            size_t go = (size_t)er * NH + kc + c;
            uint32_t so = (uint32_t)(r * (SLD * 2) + c * 2);
            CP_ASYNC16(bh + so, g_Eh + (srcsz ? go : 0), srcsz);
            CP_ASYNC16(bl + so, g_El + (srcsz ? go : 0), srcsz);
        }
    };

    fillB(0);
    asm volatile("cp.async.commit_group;" ::: "memory");

    float acc[4][4][4];
    #pragma unroll
    for (int i = 0; i < 4; i++)
        #pragma unroll
        for (int j = 0; j < 4; j++)
            { acc[i][j][0]=0.f; acc[i][j][1]=0.f; acc[i][j][2]=0.f; acc[i][j][3]=0.f; }

    for (int s = 0; s < steps; s++) {
        if (s + 1 < steps) {
            fillB(s + 1);
            asm volatile("cp.async.commit_group;" ::: "memory");
            asm volatile("cp.async.wait_group 1;" ::: "memory");
        } else {
            asm volatile("cp.async.wait_group 0;" ::: "memory");
        }
        __syncthreads();

        int stage = s & 1;
        int kA = (s & 1) * 64;                    // A k-offset for this chunk
        const char* bhp = smem + SB + stage * BSTAGE;
        const char* blp = bhp + 36864;

        #pragma unroll
        for (int ks = 0; ks < 4; ks++) {
            int k = ks * 16;
            uint32_t aH[4][4], bH[2][4], bL[2][4];
            #pragma unroll
            for (int mt = 0; mt < 4; mt++)
                LDSM_X4(aH[mt], sbase + SA_H +
                        (wm + mt * 16 + aRow) * (ALD * 2) + (kA + k + aCol) * 2);
            #pragma unroll
            for (int p = 0; p < 2; p++) {
                LDSM_X4(bH[p], smem_u32(bhp + (wn + p * 16 + bRow) * (SLD * 2) + (k + bCol) * 2));
                LDSM_X4(bL[p], smem_u32(blp + (wn + p * 16 + bRow) * (SLD * 2) + (k + bCol) * 2));
            }
            #pragma unroll
            for (int mt = 0; mt < 4; mt++)
                #pragma unroll
                for (int nt = 0; nt < 4; nt++) {
                    MMA_BF16(acc[mt][nt], aH[mt], (&bH[nt >> 1][(nt & 1) * 2]));
                    MMA_BF16(acc[mt][nt], aH[mt], (&bL[nt >> 1][(nt & 1) * 2]));
                }
            #pragma unroll
            for (int mt = 0; mt < 4; mt++) {
                uint32_t aL[4];
                LDSM_X4(aL, sbase + SA_L +
                        (wm + mt * 16 + aRow) * (ALD * 2) + (kA + k + aCol) * 2);
                #pragma unroll
                for (int nt = 0; nt < 4; nt++)
                    MMA_BF16(acc[mt][nt], aL, (&bH[nt >> 1][(nt & 1) * 2]));
            }
        }
        __syncthreads();

        if (s & 1) {
            // epilogue for this tile
            int n0 = (nstart + (s >> 1) * nstride) * 256;
            #pragma unroll
            for (int mt = 0; mt < 4; mt++) {
                int row = m0 + wm + mt * 16 + arow;
                #pragma unroll
                for (int nt = 0; nt < 4; nt++) {
                    int col = n0 + wn + nt * 8 + acol;
                    if (col < NENT) {
                        *(float2*)(out + (size_t)row * NENT + col) =
                            make_float2(acc[mt][nt][0], acc[mt][nt][1]);
                        *(float2*)(out + (size_t)(row + 8) * NENT + col) =
                            make_float2(acc[mt][nt][2], acc[mt][nt][3]);
                    }
                }
            }
            #pragma unroll
            for (int i = 0; i < 4; i++)
                #pragma unroll
                for (int j = 0; j < 4; j++)
                    { acc[i][j][0]=0.f; acc[i][j][1]=0.f; acc[i][j][2]=0.f; acc[i][j][3]=0.f; }
        }
    }
}

// ---------------- launch ----------------------------------------------------
extern "C" void kernel_launch(void* const* d_in, const int* in_sizes, int n_in,
                              void* d_out, int out_size) {
    const int*   heads        = (const int*)d_in[0];
    const int*   relations    = (const int*)d_in[1];
    const int*   times        = (const int*)d_in[2];
    const int*   hist_ent     = (const int*)d_in[3];
    const int*   hist_rel     = (const int*)d_in[4];
    const float* hist_delta   = (const float*)d_in[5];
    const float* hist_mask    = (const float*)d_in[6];
    const float* entity_emb   = (const float*)d_in[7];
    const float* relation_emb = (const float*)d_in[8];
    const float* time_emb     = (const float*)d_in[9];
    const float* delta_W      = (const float*)d_in[10];
    const float* delta_b      = (const float*)d_in[11];
    const float* query_W      = (const float*)d_in[12];
    const float* query_b      = (const float*)d_in[13];
    const float* in_W         = (const float*)d_in[14];
    const float* in_b         = (const float*)d_in[15];
    const float* a_W          = (const float*)d_in[16];
    const float* a_b          = (const float*)d_in[17];
    const float* hyper_in_W   = (const float*)d_in[18];
    const float* hyper_in_b   = (const float*)d_in[19];
    const float* hyper_gate_W = (const float*)d_in[20];
    const float* hyper_gate_b = (const float*)d_in[21];
    const float* attn_W       = (const float*)d_in[22];
    const float* attn_b       = (const float*)d_in[23];
    float* out = (float*)d_out;

    cudaFuncSetAttribute(front_kernel, cudaFuncAttributeMaxDynamicSharedMemorySize, FRONT_SMEM);
    cudaFuncSetAttribute(score_kernel, cudaFuncAttributeMaxDynamicSharedMemorySize, SCORE_SMEM);

    convertE_kernel<<<(NENT * NH / 4) / 256, 256>>>(entity_emb);
    prep_kernel<<<NREL + 2, 128>>>(relation_emb, in_W, delta_W, delta_b);
    front_kernel<<<NB, 256, FRONT_SMEM>>>(
        heads, relations, times, hist_ent, hist_rel, hist_delta, hist_mask,
        entity_emb, relation_emb, time_emb, query_W, query_b, in_W, in_b,
        a_W, a_b, hyper_in_W, hyper_in_b, hyper_gate_W, hyper_gate_b,
        attn_W, attn_b);
    score_kernel<<<148, 512, SCORE_SMEM>>>(out);
}

// round 6
// speedup vs baseline: 1.0019x; 1.0019x over previous
#include <cuda_runtime.h>
#include <cuda_bf16.h>
#include <stdint.h>

#define NB   512
#define NL   64
#define NH   128
#define NENT 200000
#define NREL 500

// ---------------- scratch (__device__ globals; no allocs allowed) ----------
__device__ float g_Rproj[NREL * NH];        // relation_emb @ in_W[128:256]
__device__ float g_vdW[NH];                 // delta_W @ in_W[256:384]
__device__ float g_vdb[NH];                 // delta_b @ in_W[256:384]
__device__ __nv_bfloat16 g_Ph[NB * NH];     // (q+ctx)*rel, bf16 hi
__device__ __nv_bfloat16 g_Pl[NB * NH];     // bf16 lo
__device__ __nv_bfloat16 g_Eh[(size_t)NENT * NH];  // entity_emb hi
__device__ __nv_bfloat16 g_El[(size_t)NENT * NH];  // entity_emb lo

// ---------------- convert entity table to split bf16 -----------------------
__global__ void convertE_kernel(const float* __restrict__ E) {
    int i = blockIdx.x * blockDim.x + threadIdx.x;      // one float4
    float4 v = ((const float4*)E)[i];
    __nv_bfloat16 h0 = __float2bfloat16(v.x);
    __nv_bfloat16 h1 = __float2bfloat16(v.y);
    __nv_bfloat16 h2 = __float2bfloat16(v.z);
    __nv_bfloat16 h3 = __float2bfloat16(v.w);
    __nv_bfloat16 l0 = __float2bfloat16(v.x - __bfloat162float(h0));
    __nv_bfloat16 l1 = __float2bfloat16(v.y - __bfloat162float(h1));
    __nv_bfloat16 l2 = __float2bfloat16(v.z - __bfloat162float(h2));
    __nv_bfloat16 l3 = __float2bfloat16(v.w - __bfloat162float(h3));
    ((__nv_bfloat162*)g_Eh)[2*i+0] = __halves2bfloat162(h0, h1);
    ((__nv_bfloat162*)g_Eh)[2*i+1] = __halves2bfloat162(h2, h3);
    ((__nv_bfloat162*)g_El)[2*i+0] = __halves2bfloat162(l0, l1);
    ((__nv_bfloat162*)g_El)[2*i+1] = __halves2bfloat162(l2, l3);
}

// ---------------- prep: fold relation/delta projections --------------------
__global__ void prep_kernel(const float* __restrict__ relation_emb,
                            const float* __restrict__ in_W,
                            const float* __restrict__ delta_W,
                            const float* __restrict__ delta_b) {
    int r = blockIdx.x, j = threadIdx.x;
    if (r < NREL) {
        __shared__ float sr[NH];
        sr[j] = relation_emb[r * NH + j];
        __syncthreads();
        float acc = 0.f;
        #pragma unroll 8
        for (int i = 0; i < NH; i++) acc += sr[i] * in_W[(NH + i) * NH + j];
        g_Rproj[r * NH + j] = acc;
    } else if (r == NREL) {
        float acc = 0.f;
        #pragma unroll 8
        for (int t = 0; t < 128; t++) acc += delta_W[t] * in_W[(256 + t) * NH + j];
        g_vdW[j] = acc;
    } else {
        float acc = 0.f;
        #pragma unroll 8
        for (int t = 0; t < 128; t++) acc += delta_b[t] * in_W[(256 + t) * NH + j];
        g_vdb[j] = acc;
    }
}

// ---------------- front: one CTA per batch row ------------------------------
#define FRONT_SMEM (19968 * 4)
__global__ __launch_bounds__(256) void front_kernel(
    const int* __restrict__ heads, const int* __restrict__ relations,
    const int* __restrict__ times, const int* __restrict__ hist_ent,
    const int* __restrict__ hist_rel, const float* __restrict__ hist_delta,
    const float* __restrict__ hist_mask, const float* __restrict__ entity_emb,
    const float* __restrict__ relation_emb, const float* __restrict__ time_emb,
    const float* __restrict__ query_W, const float* __restrict__ query_b,
    const float* __restrict__ in_W, const float* __restrict__ in_b,
    const float* __restrict__ a_W, const float* __restrict__ a_b,
    const float* __restrict__ hyper_in_W, const float* __restrict__ hyper_in_b,
    const float* __restrict__ hyper_gate_W, const float* __restrict__ hyper_gate_b,
    const float* __restrict__ attn_W, const float* __restrict__ attn_b)
{
    extern __shared__ float sm[];
    float* s_NE   = sm;
    float* s_X    = sm + 8192;
    float* s_W    = sm + 16384;
    float* s_misc = sm + 18432;
    float* s_rel    = s_misc;
    float* s_q      = s_misc + 128;
    float* s_cgate  = s_misc + 256;
    float* s_bias   = s_misc + 384;
    float* s_vdW    = s_misc + 512;
    float* s_attnW  = s_misc + 640;
    float* s_head   = s_misc + 896;
    float* s_tf     = s_misc + 1024;
    float* s_scores = s_misc + 1152;
    float* s_attn   = s_misc + 1216;
    float* s_delta  = s_misc + 1280;
    float* s_mask   = s_misc + 1344;
    int*   s_hr     = (int*)(s_misc + 1408);
    float* s_qdot   = s_misc + 1472;
    float* s_A = s_NE;

    int b = blockIdx.x, tid = threadIdx.x;

    if (tid < 128) {
        s_head[tid] = entity_emb[(size_t)heads[b] * NH + tid];
        s_rel[tid]  = relation_emb[relations[b] * NH + tid];
        s_tf[tid]   = time_emb[times[b] * NH + tid];
        s_vdW[tid]  = g_vdW[tid];
    } else {
        int j = tid - 128;
        s_attnW[j]       = attn_W[j];
        s_attnW[128 + j] = attn_W[128 + j];
    }
    if (tid < 64) {
        s_delta[tid] = hist_delta[b * NL + tid];
        s_mask[tid]  = hist_mask[b * NL + tid];
        s_hr[tid]    = hist_rel[b * NL + tid];
    }
    __syncthreads();

    if (tid < 128) {
        int j = tid;
        float acc = query_b[j];
        #pragma unroll 4
        for (int i = 0; i < 128; i++) acc += s_head[i] * query_W[i * NH + j];
        #pragma unroll 4
        for (int i = 0; i < 128; i++) acc += s_rel[i] * query_W[(128 + i) * NH + j];
        #pragma unroll 4
        for (int i = 0; i < 128; i++) acc += s_tf[i] * query_W[(256 + i) * NH + j];
        s_q[j] = acc;
    } else {
        int j = tid - 128;
        float ci = hyper_in_b[j], cg = hyper_gate_b[j];
        #pragma unroll 4
        for (int i = 0; i < 128; i++) {
            float r = s_rel[i];
            ci += r * hyper_in_W[i * NH + j];
            cg += r * hyper_gate_W[i * NH + j];
        }
        s_cgate[j] = 1.f / (1.f + __expf(-cg));
        s_bias[j]  = in_b[j] + ci + g_vdb[j];
    }
    __syncthreads();

    {
        int w = tid >> 5, lane = tid & 31;
        for (int l = w; l < NL; l += 8) {
            size_t e = (size_t)hist_ent[b * NL + l];
            ((float4*)(s_NE + l * NH))[lane] = ((const float4*)(entity_emb + e * NH))[lane];
        }
    }
    __syncthreads();

    int cgi = tid & 15, rgi = tid >> 4;
    int c0 = cgi * 8, r0 = rgi * 4;
    int wr = tid >> 4, wc = (tid & 15) * 8;
    float acc[4][8];
    float4 pw0, pw1;

    #pragma unroll
    for (int i = 0; i < 4; i++) {
        int l = r0 + i;
        float dl = s_delta[l];
        const float* rp = g_Rproj + s_hr[l] * NH + c0;
        #pragma unroll
        for (int j = 0; j < 8; j++)
            acc[i][j] = s_bias[c0 + j] + dl * s_vdW[c0 + j] + rp[j];
    }
    {
        const float4* s = (const float4*)(in_W + wr * NH + wc);
        pw0 = s[0]; pw1 = s[1];
    }
    for (int kt = 0; kt < 8; kt++) {
        __syncthreads();
        { float4* d = (float4*)(s_W + wr * NH + wc); d[0] = pw0; d[1] = pw1; }
        __syncthreads();
        if (kt < 7) {
            const float4* s = (const float4*)(in_W + ((kt + 1) * 16 + wr) * NH + wc);
            pw0 = s[0]; pw1 = s[1];
        }
        #pragma unroll
        for (int k = 0; k < 16; k++) {
            int kk = kt * 16 + k;
            float a0 = s_NE[(r0 + 0) * NH + kk];
            float a1 = s_NE[(r0 + 1) * NH + kk];
            float a2 = s_NE[(r0 + 2) * NH + kk];
            float a3 = s_NE[(r0 + 3) * NH + kk];
            float4 b0 = *(const float4*)(s_W + k * NH + c0);
            float4 b1 = *(const float4*)(s_W + k * NH + c0 + 4);
            float bb[8] = {b0.x, b0.y, b0.z, b0.w, b1.x, b1.y, b1.z, b1.w};
            #pragma unroll
            for (int j = 0; j < 8; j++) {
                acc[0][j] += a0 * bb[j]; acc[1][j] += a1 * bb[j];
                acc[2][j] += a2 * bb[j]; acc[3][j] += a3 * bb[j];
            }
        }
    }
    __syncthreads();
    #pragma unroll
    for (int i = 0; i < 4; i++)
        #pragma unroll
        for (int j = 0; j < 8; j++)
            s_X[(r0 + i) * NH + c0 + j] = acc[i][j];
    __syncthreads();

    #pragma unroll
    for (int i = 0; i < 4; i++)
        #pragma unroll
        for (int j = 0; j < 8; j++)
            acc[i][j] = a_b[c0 + j];
    {
        const float4* s = (const float4*)(a_W + wr * NH + wc);
        pw0 = s[0]; pw1 = s[1];
    }
    for (int kt = 0; kt < 8; kt++) {
        __syncthreads();
        { float4* d = (float4*)(s_W + wr * NH + wc); d[0] = pw0; d[1] = pw1; }
        __syncthreads();
        if (kt < 7) {
            const float4* s = (const float4*)(a_W + ((kt + 1) * 16 + wr) * NH + wc);
            pw0 = s[0]; pw1 = s[1];
        }
        #pragma unroll
        for (int k = 0; k < 16; k++) {
            int kk = kt * 16 + k;
            float a0 = s_X[(r0 + 0) * NH + kk];
            float a1 = s_X[(r0 + 1) * NH + kk];
            float a2 = s_X[(r0 + 2) * NH + kk];
            float a3 = s_X[(r0 + 3) * NH + kk];
            float4 b0 = *(const float4*)(s_W + k * NH + c0);
            float4 b1 = *(const float4*)(s_W + k * NH + c0 + 4);
            float bb[8] = {b0.x, b0.y, b0.z, b0.w, b1.x, b1.y, b1.z, b1.w};
            #pragma unroll
            for (int j = 0; j < 8; j++) {
                acc[0][j] += a0 * bb[j]; acc[1][j] += a1 * bb[j];
                acc[2][j] += a2 * bb[j]; acc[3][j] += a3 * bb[j];
            }
        }
    }
    __syncthreads();
    #pragma unroll
    for (int i = 0; i < 4; i++)
        #pragma unroll
        for (int j = 0; j < 8; j++)
            s_A[(r0 + i) * NH + c0 + j] = 1.f / (1.f + __expf(-acc[i][j]));
    __syncthreads();

    if (tid < 128) {
        float h = 0.f, cgt = s_cgate[tid];
        for (int l = 0; l < NL; l++) {
            float x = s_X[l * NH + tid];
            float a = s_A[l * NH + tid];
            float m = s_mask[l];
            float hn = a * h + (1.f - a) * x;
            h = m * hn + (1.f - m) * h;
            s_X[l * NH + tid] = h * cgt;
        }
    }
    __syncthreads();

    if (tid < 32) {
        float p = 0.f;
        for (int j = tid; j < 128; j += 32) p += s_q[j] * s_attnW[128 + j];
        #pragma unroll
        for (int o = 16; o; o >>= 1) p += __shfl_xor_sync(~0u, p, o);
        if (tid == 0) s_qdot[0] = p + attn_b[0];
    }
    __syncthreads();
    {
        int w = tid >> 5, lane = tid & 31;
        for (int l = w; l < NL; l += 8) {
            float p = 0.f;
            #pragma unroll
            for (int j = lane; j < 128; j += 32) p += s_X[l * NH + j] * s_attnW[j];
            #pragma unroll
            for (int o = 16; o; o >>= 1) p += __shfl_xor_sync(~0u, p, o);
            if (lane == 0) {
                float sc = tanhf(p + s_qdot[0]);
                s_scores[l] = (s_mask[l] <= 0.f) ? -1e9f : sc;
            }
        }
    }
    __syncthreads();
    if (tid < 32) {
        float v0 = s_scores[tid], v1 = s_scores[tid + 32];
        float mx = fmaxf(v0, v1);
        #pragma unroll
        for (int o = 16; o; o >>= 1) mx = fmaxf(mx, __shfl_xor_sync(~0u, mx, o));
        float e0 = __expf(v0 - mx) * s_mask[tid];
        float e1 = __expf(v1 - mx) * s_mask[tid + 32];
        float s = e0 + e1;
        #pragma unroll
        for (int o = 16; o; o >>= 1) s += __shfl_xor_sync(~0u, s, o);
        s = fmaxf(s, 1e-9f);
        s_attn[tid] = e0 / s;
        s_attn[tid + 32] = e1 / s;
    }
    __syncthreads();
    if (tid < 128) {
        float c = 0.f;
        #pragma unroll 4
        for (int l = 0; l < NL; l++) c += s_X[l * NH + tid] * s_attn[l];
        float P = (s_q[tid] + c) * s_rel[tid];
        __nv_bfloat16 hi = __float2bfloat16(P);
        float lo = P - __bfloat162float(hi);
        g_Ph[b * NH + tid] = hi;
        g_Pl[b * NH + tid] = __float2bfloat16(lo);
    }
}

// ---------------- score: persistent split-bf16 mma.sync GEMM ---------------
// 148 persistent CTAs, 512 threads. CTA: m-tile 128 (bid&3), loops n-tiles of 256.
// A (Ph/Pl full K=128) resident in smem; B (Eh/El) double-buffered via cp.async.
// MMA loops are pass-separated (H*H, H*L, L*H) so each accumulator's reuse
// distance is 16 issues -> no HMMA RAW stalls.
#define ALD 136                 // A smem row stride (bf16), 272B
#define SLD 72                  // B smem row stride per k-chunk (bf16), 144B
#define SA_H 0
#define SA_L 34816
#define SB   69632
#define BSTAGE 73728            // per stage: BH 36864 + BL 36864
#define SCORE_SMEM (SB + 2 * BSTAGE)    // 217088
#define NTILES ((NENT + 255) / 256)     // 782

#define MMA_BF16(d, a, b) asm volatile( \
    "mma.sync.aligned.m16n8k16.row.col.f32.bf16.bf16.f32 " \
    "{%0,%1,%2,%3},{%4,%5,%6,%7},{%8,%9},{%0,%1,%2,%3};" \
    : "+f"(d[0]), "+f"(d[1]), "+f"(d[2]), "+f"(d[3]) \
    : "r"(a[0]), "r"(a[1]), "r"(a[2]), "r"(a[3]), "r"(b[0]), "r"(b[1]))

#define LDSM_X4(r, addr) asm volatile( \
    "ldmatrix.sync.aligned.m8n8.x4.shared.b16 {%0,%1,%2,%3}, [%4];" \
    : "=r"((r)[0]), "=r"((r)[1]), "=r"((r)[2]), "=r"((r)[3]) : "r"(addr))

#define CP_ASYNC16(dst, src, srcsz) asm volatile( \
    "cp.async.cg.shared.global [%0], [%1], 16, %2;" \
    :: "r"(dst), "l"(src), "r"(srcsz) : "memory")

__device__ __forceinline__ uint32_t smem_u32(const void* p) {
    return (uint32_t)__cvta_generic_to_shared(p);
}

__global__ __launch_bounds__(512, 1) void score_kernel(float* __restrict__ out) {
    extern __shared__ char smem[];
    uint32_t sbase = smem_u32(smem);
    int tid = threadIdx.x, warp = tid >> 5, lane = tid & 31;
    int m0 = (blockIdx.x & 3) * 128;
    int nstart = blockIdx.x >> 2;                 // 0..36
    const int nstride = 37;

    int wm = (warp >> 3) * 64;                    // 2 warps in m
    int wn = (warp & 7) * 32;                     // 8 warps in n
    int aRow = lane & 15, aCol = (lane >> 4) * 8; // ldmatrix A
    int bRow = ((lane >> 4) << 3) + (lane & 7);   // ldmatrix B
    int bCol = ((lane >> 3) & 1) * 8;
    int arow = lane >> 2, acol = (lane & 3) * 2;  // accum layout

    // ---- A resident fill: 128 rows x 128 bf16, hi & lo ----
    #pragma unroll
    for (int i = 0; i < 4; i++) {
        int idx = tid + i * 512;                  // 0..2047
        int r = idx >> 4, c = (idx & 15) * 8;
        *(uint4*)(smem + SA_H + r * (ALD * 2) + c * 2) =
            *(const uint4*)(g_Ph + (size_t)(m0 + r) * NH + c);
        *(uint4*)(smem + SA_L + r * (ALD * 2) + c * 2) =
            *(const uint4*)(g_Pl + (size_t)(m0 + r) * NH + c);
    }

    // step s -> tile (nstart + (s>>1)*nstride), k-chunk (s&1)
    int ntiles = 0;
    for (int t = nstart; t < NTILES; t += nstride) ntiles++;
    int steps = ntiles * 2;
    if (steps == 0) return;

    // B fill for step s into stage buffer
    auto fillB = [&](int s) {
        int stage = s & 1;
        int n0 = (nstart + (s >> 1) * nstride) * 256;
        int kc = (s & 1) * 64;
        uint32_t bh = sbase + SB + stage * BSTAGE;
        uint32_t bl = bh + 36864;
        #pragma unroll
        for (int i = 0; i < 4; i++) {
            int idx = tid + i * 512;              // 0..2047
            int r = idx >> 3;                     // 0..255
            int c = (idx & 7) * 8;                // 0..56
            int er = n0 + r;
            uint32_t srcsz = (er < NENT) ? 16u : 0u;
            size_t go = (size_t)er * NH + kc + c;
            uint32_t so = (uint32_t)(r * (SLD * 2) + c * 2);
            CP_ASYNC16(bh + so, g_Eh + (srcsz ? go : 0), srcsz);
            CP_ASYNC16(bl + so, g_El + (srcsz ? go : 0), srcsz);
        }
    };

    fillB(0);
    asm volatile("cp.async.commit_group;" ::: "memory");

    float acc[4][4][4];
    #pragma unroll
    for (int i = 0; i < 4; i++)
        #pragma unroll
        for (int j = 0; j < 4; j++)
            { acc[i][j][0]=0.f; acc[i][j][1]=0.f; acc[i][j][2]=0.f; acc[i][j][3]=0.f; }

    for (int s = 0; s < steps; s++) {
        if (s + 1 < steps) {
            fillB(s + 1);
            asm volatile("cp.async.commit_group;" ::: "memory");
            asm volatile("cp.async.wait_group 1;" ::: "memory");
        } else {
            asm volatile("cp.async.wait_group 0;" ::: "memory");
        }
        __syncthreads();

        int stage = s & 1;
        int kA = (s & 1) * 64;                    // A k-offset for this chunk
        const char* bhp = smem + SB + stage * BSTAGE;
        const char* blp = bhp + 36864;

        #pragma unroll
        for (int ks = 0; ks < 4; ks++) {
            int k = ks * 16;
            uint32_t aH[4][4], bH[2][4], bL[2][4];
            #pragma unroll
            for (int mt = 0; mt < 4; mt++)
                LDSM_X4(aH[mt], sbase + SA_H +
                        (wm + mt * 16 + aRow) * (ALD * 2) + (kA + k + aCol) * 2);
            #pragma unroll
            for (int p = 0; p < 2; p++) {
                LDSM_X4(bH[p], smem_u32(bhp + (wn + p * 16 + bRow) * (SLD * 2) + (k + bCol) * 2));
                LDSM_X4(bL[p], smem_u32(blp + (wn + p * 16 + bRow) * (SLD * 2) + (k + bCol) * 2));
            }
            // pass 1: Ah * Bh — 16 independent accumulators
            #pragma unroll
            for (int mt = 0; mt < 4; mt++)
                #pragma unroll
                for (int nt = 0; nt < 4; nt++)
                    MMA_BF16(acc[mt][nt], aH[mt], (&bH[nt >> 1][(nt & 1) * 2]));
            // pass 2: Ah * Bl — reuse distance 16
            #pragma unroll
            for (int mt = 0; mt < 4; mt++)
                #pragma unroll
                for (int nt = 0; nt < 4; nt++)
                    MMA_BF16(acc[mt][nt], aH[mt], (&bL[nt >> 1][(nt & 1) * 2]));
            // pass 3: Al * Bh — double-buffered aL prefetch
            {
                uint32_t aL[2][4];
                LDSM_X4(aL[0], sbase + SA_L +
                        (wm + 0 * 16 + aRow) * (ALD * 2) + (kA + k + aCol) * 2);
                #pragma unroll
                for (int mt = 0; mt < 4; mt++) {
                    if (mt < 3)
                        LDSM_X4(aL[(mt + 1) & 1], sbase + SA_L +
                                (wm + (mt + 1) * 16 + aRow) * (ALD * 2) + (kA + k + aCol) * 2);
                    #pragma unroll
                    for (int nt = 0; nt < 4; nt++)
                        MMA_BF16(acc[mt][nt], aL[mt & 1], (&bH[nt >> 1][(nt & 1) * 2]));
                }
            }
        }
        __syncthreads();

        if (s & 1) {
            // epilogue for this tile
            int n0 = (nstart + (s >> 1) * nstride) * 256;
            #pragma unroll
            for (int mt = 0; mt < 4; mt++) {
                int row = m0 + wm + mt * 16 + arow;
                #pragma unroll
                for (int nt = 0; nt < 4; nt++) {
                    int col = n0 + wn + nt * 8 + acol;
                    if (col < NENT) {
                        *(float2*)(out + (size_t)row * NENT + col) =
                            make_float2(acc[mt][nt][0], acc[mt][nt][1]);
                        *(float2*)(out + (size_t)(row + 8) * NENT + col) =
                            make_float2(acc[mt][nt][2], acc[mt][nt][3]);
                    }
                }
            }
            #pragma unroll
            for (int i = 0; i < 4; i++)
                #pragma unroll
                for (int j = 0; j < 4; j++)
                    { acc[i][j][0]=0.f; acc[i][j][1]=0.f; acc[i][j][2]=0.f; acc[i][j][3]=0.f; }
        }
    }
}

// ---------------- launch ----------------------------------------------------
extern "C" void kernel_launch(void* const* d_in, const int* in_sizes, int n_in,
                              void* d_out, int out_size) {
    const int*   heads        = (const int*)d_in[0];
    const int*   relations    = (const int*)d_in[1];
    const int*   times        = (const int*)d_in[2];
    const int*   hist_ent     = (const int*)d_in[3];
    const int*   hist_rel     = (const int*)d_in[4];
    const float* hist_delta   = (const float*)d_in[5];
    const float* hist_mask    = (const float*)d_in[6];
    const float* entity_emb   = (const float*)d_in[7];
    const float* relation_emb = (const float*)d_in[8];
    const float* time_emb     = (const float*)d_in[9];
    const float* delta_W      = (const float*)d_in[10];
    const float* delta_b      = (const float*)d_in[11];
    const float* query_W      = (const float*)d_in[12];
    const float* query_b      = (const float*)d_in[13];
    const float* in_W         = (const float*)d_in[14];
    const float* in_b         = (const float*)d_in[15];
    const float* a_W          = (const float*)d_in[16];
    const float* a_b          = (const float*)d_in[17];
    const float* hyper_in_W   = (const float*)d_in[18];
    const float* hyper_in_b   = (const float*)d_in[19];
    const float* hyper_gate_W = (const float*)d_in[20];
    const float* hyper_gate_b = (const float*)d_in[21];
    const float* attn_W       = (const float*)d_in[22];
    const float* attn_b       = (const float*)d_in[23];
    float* out = (float*)d_out;

    cudaFuncSetAttribute(front_kernel, cudaFuncAttributeMaxDynamicSharedMemorySize, FRONT_SMEM);
    cudaFuncSetAttribute(score_kernel, cudaFuncAttributeMaxDynamicSharedMemorySize, SCORE_SMEM);

    convertE_kernel<<<(NENT * NH / 4) / 256, 256>>>(entity_emb);
    prep_kernel<<<NREL + 2, 128>>>(relation_emb, in_W, delta_W, delta_b);
    front_kernel<<<NB, 256, FRONT_SMEM>>>(
        heads, relations, times, hist_ent, hist_rel, hist_delta, hist_mask,
        entity_emb, relation_emb, time_emb, query_W, query_b, in_W, in_b,
        a_W, a_b, hyper_in_W, hyper_in_b, hyper_gate_W, hyper_gate_b,
        attn_W, attn_b);
    score_kernel<<<148, 512, SCORE_SMEM>>>(out);
}

// round 7
// speedup vs baseline: 1.1859x; 1.1836x over previous
#include <cuda_runtime.h>
#include <cuda_bf16.h>
#include <cuda_fp16.h>
#include <stdint.h>

#define NB   512
#define NL   64
#define NH   128
#define NENT 200000
#define NREL 500

// ---------------- scratch (__device__ globals; no allocs allowed) ----------
__device__ float g_Rproj[NREL * NH];        // relation_emb @ in_W[128:256]
__device__ float g_vdW[NH];                 // delta_W @ in_W[256:384]
__device__ float g_vdb[NH];                 // delta_b @ in_W[256:384]
__device__ __half g_Ph[NB * NH];            // (q+ctx)*rel, fp16 hi
__device__ __half g_Pl[NB * NH];            // fp16 residual
__device__ __half g_Eh[(size_t)NENT * NH];  // entity_emb rounded to fp16

// ---------------- convert entity table to fp16 ------------------------------
__global__ void convertE_kernel(const float* __restrict__ E) {
    int i = blockIdx.x * blockDim.x + threadIdx.x;      // one float4
    float4 v = ((const float4*)E)[i];
    __half2 h0 = __floats2half2_rn(v.x, v.y);
    __half2 h1 = __floats2half2_rn(v.z, v.w);
    ((__half2*)g_Eh)[2*i+0] = h0;
    ((__half2*)g_Eh)[2*i+1] = h1;
}

// ---------------- prep: fold relation/delta projections --------------------
__global__ void prep_kernel(const float* __restrict__ relation_emb,
                            const float* __restrict__ in_W,
                            const float* __restrict__ delta_W,
                            const float* __restrict__ delta_b) {
    int r = blockIdx.x, j = threadIdx.x;
    if (r < NREL) {
        __shared__ float sr[NH];
        sr[j] = relation_emb[r * NH + j];
        __syncthreads();
        float acc = 0.f;
        #pragma unroll 8
        for (int i = 0; i < NH; i++) acc += sr[i] * in_W[(NH + i) * NH + j];
        g_Rproj[r * NH + j] = acc;
    } else if (r == NREL) {
        float acc = 0.f;
        #pragma unroll 8
        for (int t = 0; t < 128; t++) acc += delta_W[t] * in_W[(256 + t) * NH + j];
        g_vdW[j] = acc;
    } else {
        float acc = 0.f;
        #pragma unroll 8
        for (int t = 0; t < 128; t++) acc += delta_b[t] * in_W[(256 + t) * NH + j];
        g_vdb[j] = acc;
    }
}

// ---------------- front: one CTA per batch row ------------------------------
#define FRONT_SMEM (19968 * 4)
__global__ __launch_bounds__(256) void front_kernel(
    const int* __restrict__ heads, const int* __restrict__ relations,
    const int* __restrict__ times, const int* __restrict__ hist_ent,
    const int* __restrict__ hist_rel, const float* __restrict__ hist_delta,
    const float* __restrict__ hist_mask, const float* __restrict__ entity_emb,
    const float* __restrict__ relation_emb, const float* __restrict__ time_emb,
    const float* __restrict__ query_W, const float* __restrict__ query_b,
    const float* __restrict__ in_W, const float* __restrict__ in_b,
    const float* __restrict__ a_W, const float* __restrict__ a_b,
    const float* __restrict__ hyper_in_W, const float* __restrict__ hyper_in_b,
    const float* __restrict__ hyper_gate_W, const float* __restrict__ hyper_gate_b,
    const float* __restrict__ attn_W, const float* __restrict__ attn_b)
{
    extern __shared__ float sm[];
    float* s_NE   = sm;
    float* s_X    = sm + 8192;
    float* s_W    = sm + 16384;
    float* s_misc = sm + 18432;
    float* s_rel    = s_misc;
    float* s_q      = s_misc + 128;
    float* s_cgate  = s_misc + 256;
    float* s_bias   = s_misc + 384;
    float* s_vdW    = s_misc + 512;
    float* s_attnW  = s_misc + 640;
    float* s_head   = s_misc + 896;
    float* s_tf     = s_misc + 1024;
    float* s_scores = s_misc + 1152;
    float* s_attn   = s_misc + 1216;
    float* s_delta  = s_misc + 1280;
    float* s_mask   = s_misc + 1344;
    int*   s_hr     = (int*)(s_misc + 1408);
    float* s_qdot   = s_misc + 1472;
    float* s_A = s_NE;

    int b = blockIdx.x, tid = threadIdx.x;

    if (tid < 128) {
        s_head[tid] = entity_emb[(size_t)heads[b] * NH + tid];
        s_rel[tid]  = relation_emb[relations[b] * NH + tid];
        s_tf[tid]   = time_emb[times[b] * NH + tid];
        s_vdW[tid]  = g_vdW[tid];
    } else {
        int j = tid - 128;
        s_attnW[j]       = attn_W[j];
        s_attnW[128 + j] = attn_W[128 + j];
    }
    if (tid < 64) {
        s_delta[tid] = hist_delta[b * NL + tid];
        s_mask[tid]  = hist_mask[b * NL + tid];
        s_hr[tid]    = hist_rel[b * NL + tid];
    }
    __syncthreads();

    if (tid < 128) {
        int j = tid;
        float acc = query_b[j];
        #pragma unroll 4
        for (int i = 0; i < 128; i++) acc += s_head[i] * query_W[i * NH + j];
        #pragma unroll 4
        for (int i = 0; i < 128; i++) acc += s_rel[i] * query_W[(128 + i) * NH + j];
        #pragma unroll 4
        for (int i = 0; i < 128; i++) acc += s_tf[i] * query_W[(256 + i) * NH + j];
        s_q[j] = acc;
    } else {
        int j = tid - 128;
        float ci = hyper_in_b[j], cg = hyper_gate_b[j];
        #pragma unroll 4
        for (int i = 0; i < 128; i++) {
            float r = s_rel[i];
            ci += r * hyper_in_W[i * NH + j];
            cg += r * hyper_gate_W[i * NH + j];
        }
        s_cgate[j] = 1.f / (1.f + __expf(-cg));
        s_bias[j]  = in_b[j] + ci + g_vdb[j];
    }
    __syncthreads();

    {
        int w = tid >> 5, lane = tid & 31;
        for (int l = w; l < NL; l += 8) {
            size_t e = (size_t)hist_ent[b * NL + l];
            ((float4*)(s_NE + l * NH))[lane] = ((const float4*)(entity_emb + e * NH))[lane];
        }
    }
    __syncthreads();

    int cgi = tid & 15, rgi = tid >> 4;
    int c0 = cgi * 8, r0 = rgi * 4;
    int wr = tid >> 4, wc = (tid & 15) * 8;
    float acc[4][8];
    float4 pw0, pw1;

    #pragma unroll
    for (int i = 0; i < 4; i++) {
        int l = r0 + i;
        float dl = s_delta[l];
        const float* rp = g_Rproj + s_hr[l] * NH + c0;
        #pragma unroll
        for (int j = 0; j < 8; j++)
            acc[i][j] = s_bias[c0 + j] + dl * s_vdW[c0 + j] + rp[j];
    }
    {
        const float4* s = (const float4*)(in_W + wr * NH + wc);
        pw0 = s[0]; pw1 = s[1];
    }
    for (int kt = 0; kt < 8; kt++) {
        __syncthreads();
        { float4* d = (float4*)(s_W + wr * NH + wc); d[0] = pw0; d[1] = pw1; }
        __syncthreads();
        if (kt < 7) {
            const float4* s = (const float4*)(in_W + ((kt + 1) * 16 + wr) * NH + wc);
            pw0 = s[0]; pw1 = s[1];
        }
        #pragma unroll
        for (int k = 0; k < 16; k++) {
            int kk = kt * 16 + k;
            float a0 = s_NE[(r0 + 0) * NH + kk];
            float a1 = s_NE[(r0 + 1) * NH + kk];
            float a2 = s_NE[(r0 + 2) * NH + kk];
            float a3 = s_NE[(r0 + 3) * NH + kk];
            float4 b0 = *(const float4*)(s_W + k * NH + c0);
            float4 b1 = *(const float4*)(s_W + k * NH + c0 + 4);
            float bb[8] = {b0.x, b0.y, b0.z, b0.w, b1.x, b1.y, b1.z, b1.w};
            #pragma unroll
            for (int j = 0; j < 8; j++) {
                acc[0][j] += a0 * bb[j]; acc[1][j] += a1 * bb[j];
                acc[2][j] += a2 * bb[j]; acc[3][j] += a3 * bb[j];
            }
        }
    }
    __syncthreads();
    #pragma unroll
    for (int i = 0; i < 4; i++)
        #pragma unroll
        for (int j = 0; j < 8; j++)
            s_X[(r0 + i) * NH + c0 + j] = acc[i][j];
    __syncthreads();

    #pragma unroll
    for (int i = 0; i < 4; i++)
        #pragma unroll
        for (int j = 0; j < 8; j++)
            acc[i][j] = a_b[c0 + j];
    {
        const float4* s = (const float4*)(a_W + wr * NH + wc);
        pw0 = s[0]; pw1 = s[1];
    }
    for (int kt = 0; kt < 8; kt++) {
        __syncthreads();
        { float4* d = (float4*)(s_W + wr * NH + wc); d[0] = pw0; d[1] = pw1; }
        __syncthreads();
        if (kt < 7) {
            const float4* s = (const float4*)(a_W + ((kt + 1) * 16 + wr) * NH + wc);
            pw0 = s[0]; pw1 = s[1];
        }
        #pragma unroll
        for (int k = 0; k < 16; k++) {
            int kk = kt * 16 + k;
            float a0 = s_X[(r0 + 0) * NH + kk];
            float a1 = s_X[(r0 + 1) * NH + kk];
            float a2 = s_X[(r0 + 2) * NH + kk];
            float a3 = s_X[(r0 + 3) * NH + kk];
            float4 b0 = *(const float4*)(s_W + k * NH + c0);
            float4 b1 = *(const float4*)(s_W + k * NH + c0 + 4);
            float bb[8] = {b0.x, b0.y, b0.z, b0.w, b1.x, b1.y, b1.z, b1.w};
            #pragma unroll
            for (int j = 0; j < 8; j++) {
                acc[0][j] += a0 * bb[j]; acc[1][j] += a1 * bb[j];
                acc[2][j] += a2 * bb[j]; acc[3][j] += a3 * bb[j];
            }
        }
    }
    __syncthreads();
    #pragma unroll
    for (int i = 0; i < 4; i++)
        #pragma unroll
        for (int j = 0; j < 8; j++)
            s_A[(r0 + i) * NH + c0 + j] = 1.f / (1.f + __expf(-acc[i][j]));
    __syncthreads();

    if (tid < 128) {
        float h = 0.f, cgt = s_cgate[tid];
        for (int l = 0; l < NL; l++) {
            float x = s_X[l * NH + tid];
            float a = s_A[l * NH + tid];
            float m = s_mask[l];
            float hn = a * h + (1.f - a) * x;
            h = m * hn + (1.f - m) * h;
            s_X[l * NH + tid] = h * cgt;
        }
    }
    __syncthreads();

    if (tid < 32) {
        float p = 0.f;
        for (int j = tid; j < 128; j += 32) p += s_q[j] * s_attnW[128 + j];
        #pragma unroll
        for (int o = 16; o; o >>= 1) p += __shfl_xor_sync(~0u, p, o);
        if (tid == 0) s_qdot[0] = p + attn_b[0];
    }
    __syncthreads();
    {
        int w = tid >> 5, lane = tid & 31;
        for (int l = w; l < NL; l += 8) {
            float p = 0.f;
            #pragma unroll
            for (int j = lane; j < 128; j += 32) p += s_X[l * NH + j] * s_attnW[j];
            #pragma unroll
            for (int o = 16; o; o >>= 1) p += __shfl_xor_sync(~0u, p, o);
            if (lane == 0) {
                float sc = tanhf(p + s_qdot[0]);
                s_scores[l] = (s_mask[l] <= 0.f) ? -1e9f : sc;
            }
        }
    }
    __syncthreads();
    if (tid < 32) {
        float v0 = s_scores[tid], v1 = s_scores[tid + 32];
        float mx = fmaxf(v0, v1);
        #pragma unroll
        for (int o = 16; o; o >>= 1) mx = fmaxf(mx, __shfl_xor_sync(~0u, mx, o));
        float e0 = __expf(v0 - mx) * s_mask[tid];
        float e1 = __expf(v1 - mx) * s_mask[tid + 32];
        float s = e0 + e1;
        #pragma unroll
        for (int o = 16; o; o >>= 1) s += __shfl_xor_sync(~0u, s, o);
        s = fmaxf(s, 1e-9f);
        s_attn[tid] = e0 / s;
        s_attn[tid + 32] = e1 / s;
    }
    __syncthreads();
    if (tid < 128) {
        float c = 0.f;
        #pragma unroll 4
        for (int l = 0; l < NL; l++) c += s_X[l * NH + tid] * s_attn[l];
        float P = (s_q[tid] + c) * s_rel[tid];
        __half hi = __float2half_rn(P);
        float lo = P - __half2float(hi);
        g_Ph[b * NH + tid] = hi;
        g_Pl[b * NH + tid] = __float2half_rn(lo);
    }
}

// ---------------- score: persistent fp16 2-term mma.sync GEMM --------------
// D = Ah*Bh + Al*Bh where A = Ah + Al (fp16 split, err ~2^-21) and
// Bh = fp16(E) (err <= 2^-11). Output norm rel err ~1.5e-4 << 1e-3.
// 148 persistent CTAs, 512 threads. A resident; B double-buffered cp.async.
#define ALD 136                 // A smem row stride (fp16), 272B
#define SLD 72                  // B smem row stride per k-chunk (fp16), 144B
#define SA_H 0
#define SA_L 34816
#define SB   69632
#define BSTAGE 36864            // per stage: BH only
#define SCORE_SMEM (SB + 2 * BSTAGE)    // 143360
#define NTILES ((NENT + 255) / 256)     // 782

#define MMA_F16(d, a, b) asm volatile( \
    "mma.sync.aligned.m16n8k16.row.col.f32.f16.f16.f32 " \
    "{%0,%1,%2,%3},{%4,%5,%6,%7},{%8,%9},{%0,%1,%2,%3};" \
    : "+f"(d[0]), "+f"(d[1]), "+f"(d[2]), "+f"(d[3]) \
    : "r"(a[0]), "r"(a[1]), "r"(a[2]), "r"(a[3]), "r"(b[0]), "r"(b[1]))

#define LDSM_X4(r, addr) asm volatile( \
    "ldmatrix.sync.aligned.m8n8.x4.shared.b16 {%0,%1,%2,%3}, [%4];" \
    : "=r"((r)[0]), "=r"((r)[1]), "=r"((r)[2]), "=r"((r)[3]) : "r"(addr))

#define CP_ASYNC16(dst, src, srcsz) asm volatile( \
    "cp.async.cg.shared.global [%0], [%1], 16, %2;" \
    :: "r"(dst), "l"(src), "r"(srcsz) : "memory")

__device__ __forceinline__ uint32_t smem_u32(const void* p) {
    return (uint32_t)__cvta_generic_to_shared(p);
}

__global__ __launch_bounds__(512, 1) void score_kernel(float* __restrict__ out) {
    extern __shared__ char smem[];
    uint32_t sbase = smem_u32(smem);
    int tid = threadIdx.x, warp = tid >> 5, lane = tid & 31;
    int m0 = (blockIdx.x & 3) * 128;
    int nstart = blockIdx.x >> 2;                 // 0..36
    const int nstride = 37;

    int wm = (warp >> 3) * 64;                    // 2 warps in m
    int wn = (warp & 7) * 32;                     // 8 warps in n
    int aRow = lane & 15, aCol = (lane >> 4) * 8; // ldmatrix A
    int bRow = ((lane >> 4) << 3) + (lane & 7);   // ldmatrix B
    int bCol = ((lane >> 3) & 1) * 8;
    int arow = lane >> 2, acol = (lane & 3) * 2;  // accum layout

    // ---- A resident fill: 128 rows x 128 fp16, hi & lo ----
    #pragma unroll
    for (int i = 0; i < 4; i++) {
        int idx = tid + i * 512;                  // 0..2047
        int r = idx >> 4, c = (idx & 15) * 8;
        *(uint4*)(smem + SA_H + r * (ALD * 2) + c * 2) =
            *(const uint4*)(g_Ph + (size_t)(m0 + r) * NH + c);
        *(uint4*)(smem + SA_L + r * (ALD * 2) + c * 2) =
            *(const uint4*)(g_Pl + (size_t)(m0 + r) * NH + c);
    }

    // step s -> tile (nstart + (s>>1)*nstride), k-chunk (s&1)
    int ntiles = 0;
    for (int t = nstart; t < NTILES; t += nstride) ntiles++;
    int steps = ntiles * 2;
    if (steps == 0) return;

    // B fill for step s into stage buffer (hi only)
    auto fillB = [&](int s) {
        int stage = s & 1;
        int n0 = (nstart + (s >> 1) * nstride) * 256;
        int kc = (s & 1) * 64;
        uint32_t bh = sbase + SB + stage * BSTAGE;
        #pragma unroll
        for (int i = 0; i < 4; i++) {
            int idx = tid + i * 512;              // 0..2047
            int r = idx >> 3;                     // 0..255
            int c = (idx & 7) * 8;                // 0..56
            int er = n0 + r;
            uint32_t srcsz = (er < NENT) ? 16u : 0u;
            size_t go = (size_t)er * NH + kc + c;
            uint32_t so = (uint32_t)(r * (SLD * 2) + c * 2);
            CP_ASYNC16(bh + so, g_Eh + (srcsz ? go : 0), srcsz);
        }
    };

    fillB(0);
    asm volatile("cp.async.commit_group;" ::: "memory");

    float acc[4][4][4];
    #pragma unroll
    for (int i = 0; i < 4; i++)
        #pragma unroll
        for (int j = 0; j < 4; j++)
            { acc[i][j][0]=0.f; acc[i][j][1]=0.f; acc[i][j][2]=0.f; acc[i][j][3]=0.f; }

    for (int s = 0; s < steps; s++) {
        if (s + 1 < steps) {
            fillB(s + 1);
            asm volatile("cp.async.commit_group;" ::: "memory");
            asm volatile("cp.async.wait_group 1;" ::: "memory");
        } else {
            asm volatile("cp.async.wait_group 0;" ::: "memory");
        }
        __syncthreads();

        int stage = s & 1;
        int kA = (s & 1) * 64;                    // A k-offset for this chunk
        const char* bhp = smem + SB + stage * BSTAGE;

        #pragma unroll
        for (int ks = 0; ks < 4; ks++) {
            int k = ks * 16;
            uint32_t aH[4][4], bH[2][4];
            #pragma unroll
            for (int mt = 0; mt < 4; mt++)
                LDSM_X4(aH[mt], sbase + SA_H +
                        (wm + mt * 16 + aRow) * (ALD * 2) + (kA + k + aCol) * 2);
            #pragma unroll
            for (int p = 0; p < 2; p++)
                LDSM_X4(bH[p], smem_u32(bhp + (wn + p * 16 + bRow) * (SLD * 2) + (k + bCol) * 2));
            // pass 1: Ah * Bh — 16 independent accumulators
            #pragma unroll
            for (int mt = 0; mt < 4; mt++)
                #pragma unroll
                for (int nt = 0; nt < 4; nt++)
                    MMA_F16(acc[mt][nt], aH[mt], (&bH[nt >> 1][(nt & 1) * 2]));
            // pass 2: Al * Bh — double-buffered aL prefetch
            {
                uint32_t aL[2][4];
                LDSM_X4(aL[0], sbase + SA_L +
                        (wm + 0 * 16 + aRow) * (ALD * 2) + (kA + k + aCol) * 2);
                #pragma unroll
                for (int mt = 0; mt < 4; mt++) {
                    if (mt < 3)
                        LDSM_X4(aL[(mt + 1) & 1], sbase + SA_L +
                                (wm + (mt + 1) * 16 + aRow) * (ALD * 2) + (kA + k + aCol) * 2);
                    #pragma unroll
                    for (int nt = 0; nt < 4; nt++)
                        MMA_F16(acc[mt][nt], aL[mt & 1], (&bH[nt >> 1][(nt & 1) * 2]));
                }
            }
        }
        __syncthreads();

        if (s & 1) {
            // epilogue for this tile
            int n0 = (nstart + (s >> 1) * nstride) * 256;
            #pragma unroll
            for (int mt = 0; mt < 4; mt++) {
                int row = m0 + wm + mt * 16 + arow;
                #pragma unroll
                for (int nt = 0; nt < 4; nt++) {
                    int col = n0 + wn + nt * 8 + acol;
                    if (col < NENT) {
                        *(float2*)(out + (size_t)row * NENT + col) =
                            make_float2(acc[mt][nt][0], acc[mt][nt][1]);
                        *(float2*)(out + (size_t)(row + 8) * NENT + col) =
                            make_float2(acc[mt][nt][2], acc[mt][nt][3]);
                    }
                }
            }
            #pragma unroll
            for (int i = 0; i < 4; i++)
                #pragma unroll
                for (int j = 0; j < 4; j++)
                    { acc[i][j][0]=0.f; acc[i][j][1]=0.f; acc[i][j][2]=0.f; acc[i][j][3]=0.f; }
        }
    }
}

// ---------------- launch ----------------------------------------------------
extern "C" void kernel_launch(void* const* d_in, const int* in_sizes, int n_in,
                              void* d_out, int out_size) {
    const int*   heads        = (const int*)d_in[0];
    const int*   relations    = (const int*)d_in[1];
    const int*   times        = (const int*)d_in[2];
    const int*   hist_ent     = (const int*)d_in[3];
    const int*   hist_rel     = (const int*)d_in[4];
    const float* hist_delta   = (const float*)d_in[5];
    const float* hist_mask    = (const float*)d_in[6];
    const float* entity_emb   = (const float*)d_in[7];
    const float* relation_emb = (const float*)d_in[8];
    const float* time_emb     = (const float*)d_in[9];
    const float* delta_W      = (const float*)d_in[10];
    const float* delta_b      = (const float*)d_in[11];
    const float* query_W      = (const float*)d_in[12];
    const float* query_b      = (const float*)d_in[13];
    const float* in_W         = (const float*)d_in[14];
    const float* in_b         = (const float*)d_in[15];
    const float* a_W          = (const float*)d_in[16];
    const float* a_b          = (const float*)d_in[17];
    const float* hyper_in_W   = (const float*)d_in[18];
    const float* hyper_in_b   = (const float*)d_in[19];
    const float* hyper_gate_W = (const float*)d_in[20];
    const float* hyper_gate_b = (const float*)d_in[21];
    const float* attn_W       = (const float*)d_in[22];
    const float* attn_b       = (const float*)d_in[23];
    float* out = (float*)d_out;

    cudaFuncSetAttribute(front_kernel, cudaFuncAttributeMaxDynamicSharedMemorySize, FRONT_SMEM);
    cudaFuncSetAttribute(score_kernel, cudaFuncAttributeMaxDynamicSharedMemorySize, SCORE_SMEM);

    convertE_kernel<<<(NENT * NH / 4) / 256, 256>>>(entity_emb);
    prep_kernel<<<NREL + 2, 128>>>(relation_emb, in_W, delta_W, delta_b);
    front_kernel<<<NB, 256, FRONT_SMEM>>>(
        heads, relations, times, hist_ent, hist_rel, hist_delta, hist_mask,
        entity_emb, relation_emb, time_emb, query_W, query_b, in_W, in_b,
        a_W, a_b, hyper_in_W, hyper_in_b, hyper_gate_W, hyper_gate_b,
        attn_W, attn_b);
    score_kernel<<<148, 512, SCORE_SMEM>>>(out);
}

// round 8
// speedup vs baseline: 1.4916x; 1.2577x over previous
#include <cuda_runtime.h>
#include <cuda_bf16.h>
#include <cuda_fp16.h>
#include <stdint.h>

#define NB   512
#define NL   64
#define NH   128
#define NENT 200000
#define NREL 500

// ---------------- scratch (__device__ globals; no allocs allowed) ----------
__device__ float g_Rproj[NREL * NH];        // relation_emb @ in_W[128:256]
__device__ float g_vdW[NH];                 // delta_W @ in_W[256:384]
__device__ float g_vdb[NH];                 // delta_b @ in_W[256:384]
__device__ __half g_Ph[NB * NH];            // (q+ctx)*rel, fp16
__device__ __half g_Eh[(size_t)NENT * NH];  // entity_emb rounded to fp16

// ---------------- convert entity table to fp16 ------------------------------
__global__ void convertE_kernel(const float* __restrict__ E) {
    int i = blockIdx.x * blockDim.x + threadIdx.x;      // one float4
    float4 v = ((const float4*)E)[i];
    __half2 h0 = __floats2half2_rn(v.x, v.y);
    __half2 h1 = __floats2half2_rn(v.z, v.w);
    ((__half2*)g_Eh)[2*i+0] = h0;
    ((__half2*)g_Eh)[2*i+1] = h1;
}

// ---------------- prep: fold relation/delta projections --------------------
__global__ void prep_kernel(const float* __restrict__ relation_emb,
                            const float* __restrict__ in_W,
                            const float* __restrict__ delta_W,
                            const float* __restrict__ delta_b) {
    int r = blockIdx.x, j = threadIdx.x;
    if (r < NREL) {
        __shared__ float sr[NH];
        sr[j] = relation_emb[r * NH + j];
        __syncthreads();
        float acc = 0.f;
        #pragma unroll 8
        for (int i = 0; i < NH; i++) acc += sr[i] * in_W[(NH + i) * NH + j];
        g_Rproj[r * NH + j] = acc;
    } else if (r == NREL) {
        float acc = 0.f;
        #pragma unroll 8
        for (int t = 0; t < 128; t++) acc += delta_W[t] * in_W[(256 + t) * NH + j];
        g_vdW[j] = acc;
    } else {
        float acc = 0.f;
        #pragma unroll 8
        for (int t = 0; t < 128; t++) acc += delta_b[t] * in_W[(256 + t) * NH + j];
        g_vdb[j] = acc;
    }
}

// ---------------- front: one CTA per batch row ------------------------------
// smem: NE/A 8192 | X 8192 | W double-buffer 4096 | misc 1536  = 22016 floats
#define FRONT_SMEM (22016 * 4)
__global__ __launch_bounds__(256) void front_kernel(
    const int* __restrict__ heads, const int* __restrict__ relations,
    const int* __restrict__ times, const int* __restrict__ hist_ent,
    const int* __restrict__ hist_rel, const float* __restrict__ hist_delta,
    const float* __restrict__ hist_mask, const float* __restrict__ entity_emb,
    const float* __restrict__ relation_emb, const float* __restrict__ time_emb,
    const float* __restrict__ query_W, const float* __restrict__ query_b,
    const float* __restrict__ in_W, const float* __restrict__ in_b,
    const float* __restrict__ a_W, const float* __restrict__ a_b,
    const float* __restrict__ hyper_in_W, const float* __restrict__ hyper_in_b,
    const float* __restrict__ hyper_gate_W, const float* __restrict__ hyper_gate_b,
    const float* __restrict__ attn_W, const float* __restrict__ attn_b)
{
    extern __shared__ float sm[];
    float* s_NE   = sm;
    float* s_X    = sm + 8192;
    float* s_W    = sm + 16384;          // 2 x 2048 floats
    float* s_misc = sm + 20480;
    float* s_rel    = s_misc;
    float* s_q      = s_misc + 128;
    float* s_cgate  = s_misc + 256;
    float* s_bias   = s_misc + 384;
    float* s_vdW    = s_misc + 512;
    float* s_attnW  = s_misc + 640;
    float* s_head   = s_misc + 896;
    float* s_tf     = s_misc + 1024;
    float* s_scores = s_misc + 1152;
    float* s_attn   = s_misc + 1216;
    float* s_delta  = s_misc + 1280;
    float* s_mask   = s_misc + 1344;
    int*   s_hr     = (int*)(s_misc + 1408);
    float* s_qdot   = s_misc + 1472;
    float* s_A = s_NE;

    int b = blockIdx.x, tid = threadIdx.x;

    if (tid < 128) {
        s_head[tid] = entity_emb[(size_t)heads[b] * NH + tid];
        s_rel[tid]  = relation_emb[relations[b] * NH + tid];
        s_tf[tid]   = time_emb[times[b] * NH + tid];
        s_vdW[tid]  = g_vdW[tid];
    } else {
        int j = tid - 128;
        s_attnW[j]       = attn_W[j];
        s_attnW[128 + j] = attn_W[128 + j];
    }
    if (tid < 64) {
        s_delta[tid] = hist_delta[b * NL + tid];
        s_mask[tid]  = hist_mask[b * NL + tid];
        s_hr[tid]    = hist_rel[b * NL + tid];
    }
    __syncthreads();

    if (tid < 128) {
        int j = tid;
        float p0 = query_b[j], p1 = 0.f, p2 = 0.f, p3 = 0.f;
        #pragma unroll 4
        for (int i = 0; i < 128; i += 4) {
            p0 += s_head[i+0] * query_W[(i+0) * NH + j];
            p1 += s_head[i+1] * query_W[(i+1) * NH + j];
            p2 += s_head[i+2] * query_W[(i+2) * NH + j];
            p3 += s_head[i+3] * query_W[(i+3) * NH + j];
        }
        #pragma unroll 4
        for (int i = 0; i < 128; i += 4) {
            p0 += s_rel[i+0] * query_W[(128+i+0) * NH + j];
            p1 += s_rel[i+1] * query_W[(128+i+1) * NH + j];
            p2 += s_rel[i+2] * query_W[(128+i+2) * NH + j];
            p3 += s_rel[i+3] * query_W[(128+i+3) * NH + j];
        }
        #pragma unroll 4
        for (int i = 0; i < 128; i += 4) {
            p0 += s_tf[i+0] * query_W[(256+i+0) * NH + j];
            p1 += s_tf[i+1] * query_W[(256+i+1) * NH + j];
            p2 += s_tf[i+2] * query_W[(256+i+2) * NH + j];
            p3 += s_tf[i+3] * query_W[(256+i+3) * NH + j];
        }
        s_q[j] = (p0 + p1) + (p2 + p3);
    } else {
        int j = tid - 128;
        float c0 = hyper_in_b[j], c1 = 0.f;
        float g0 = hyper_gate_b[j], g1 = 0.f;
        #pragma unroll 4
        for (int i = 0; i < 128; i += 2) {
            float r0 = s_rel[i], r1 = s_rel[i+1];
            c0 += r0 * hyper_in_W[i * NH + j];
            c1 += r1 * hyper_in_W[(i+1) * NH + j];
            g0 += r0 * hyper_gate_W[i * NH + j];
            g1 += r1 * hyper_gate_W[(i+1) * NH + j];
        }
        s_cgate[j] = 1.f / (1.f + __expf(-(g0 + g1)));
        s_bias[j]  = in_b[j] + (c0 + c1) + g_vdb[j];
    }
    __syncthreads();

    {
        int w = tid >> 5, lane = tid & 31;
        for (int l = w; l < NL; l += 8) {
            size_t e = (size_t)hist_ent[b * NL + l];
            ((float4*)(s_NE + l * NH))[lane] = ((const float4*)(entity_emb + e * NH))[lane];
        }
    }
    __syncthreads();

    int cgi = tid & 15, rgi = tid >> 4;
    int c0 = cgi * 8, r0 = rgi * 4;
    int wr = tid >> 4, wc = (tid & 15) * 8;
    float acc[4][8];

    #pragma unroll
    for (int i = 0; i < 4; i++) {
        int l = r0 + i;
        float dl = s_delta[l];
        const float* rp = g_Rproj + s_hr[l] * NH + c0;
        #pragma unroll
        for (int j = 0; j < 8; j++)
            acc[i][j] = s_bias[c0 + j] + dl * s_vdW[c0 + j] + rp[j];
    }
    // GEMM 1: X = NE @ in_W[0:128] (+bias), W double-buffered
    {
        const float4* s = (const float4*)(in_W + wr * NH + wc);
        float4 t0 = s[0], t1 = s[1];
        float4* d = (float4*)(s_W + wr * NH + wc);
        d[0] = t0; d[1] = t1;
    }
    __syncthreads();
    for (int kt = 0; kt < 8; kt++) {
        if (kt < 7) {
            const float4* s = (const float4*)(in_W + ((kt + 1) * 16 + wr) * NH + wc);
            float4 t0 = s[0], t1 = s[1];
            float4* d = (float4*)(s_W + ((kt + 1) & 1) * 2048 + wr * NH + wc);
            d[0] = t0; d[1] = t1;
        }
        const float* Wb = s_W + (kt & 1) * 2048;
        #pragma unroll
        for (int k = 0; k < 16; k++) {
            int kk = kt * 16 + k;
            float a0 = s_NE[(r0 + 0) * NH + kk];
            float a1 = s_NE[(r0 + 1) * NH + kk];
            float a2 = s_NE[(r0 + 2) * NH + kk];
            float a3 = s_NE[(r0 + 3) * NH + kk];
            float4 b0 = *(const float4*)(Wb + k * NH + c0);
            float4 b1 = *(const float4*)(Wb + k * NH + c0 + 4);
            float bb[8] = {b0.x, b0.y, b0.z, b0.w, b1.x, b1.y, b1.z, b1.w};
            #pragma unroll
            for (int j = 0; j < 8; j++) {
                acc[0][j] += a0 * bb[j]; acc[1][j] += a1 * bb[j];
                acc[2][j] += a2 * bb[j]; acc[3][j] += a3 * bb[j];
            }
        }
        __syncthreads();
    }
    #pragma unroll
    for (int i = 0; i < 4; i++)
        #pragma unroll
        for (int j = 0; j < 8; j++)
            s_X[(r0 + i) * NH + c0 + j] = acc[i][j];
    __syncthreads();

    // GEMM 2: A = sigmoid(X @ a_W + a_b)
    #pragma unroll
    for (int i = 0; i < 4; i++)
        #pragma unroll
        for (int j = 0; j < 8; j++)
            acc[i][j] = a_b[c0 + j];
    {
        const float4* s = (const float4*)(a_W + wr * NH + wc);
        float4 t0 = s[0], t1 = s[1];
        float4* d = (float4*)(s_W + wr * NH + wc);
        d[0] = t0; d[1] = t1;
    }
    __syncthreads();
    for (int kt = 0; kt < 8; kt++) {
        if (kt < 7) {
            const float4* s = (const float4*)(a_W + ((kt + 1) * 16 + wr) * NH + wc);
            float4 t0 = s[0], t1 = s[1];
            float4* d = (float4*)(s_W + ((kt + 1) & 1) * 2048 + wr * NH + wc);
            d[0] = t0; d[1] = t1;
        }
        const float* Wb = s_W + (kt & 1) * 2048;
        #pragma unroll
        for (int k = 0; k < 16; k++) {
            int kk = kt * 16 + k;
            float a0 = s_X[(r0 + 0) * NH + kk];
            float a1 = s_X[(r0 + 1) * NH + kk];
            float a2 = s_X[(r0 + 2) * NH + kk];
            float a3 = s_X[(r0 + 3) * NH + kk];
            float4 b0 = *(const float4*)(Wb + k * NH + c0);
            float4 b1 = *(const float4*)(Wb + k * NH + c0 + 4);
            float bb[8] = {b0.x, b0.y, b0.z, b0.w, b1.x, b1.y, b1.z, b1.w};
            #pragma unroll
            for (int j = 0; j < 8; j++) {
                acc[0][j] += a0 * bb[j]; acc[1][j] += a1 * bb[j];
                acc[2][j] += a2 * bb[j]; acc[3][j] += a3 * bb[j];
            }
        }
        __syncthreads();
    }
    #pragma unroll
    for (int i = 0; i < 4; i++)
        #pragma unroll
        for (int j = 0; j < 8; j++)
            s_A[(r0 + i) * NH + c0 + j] = 1.f / (1.f + __expf(-acc[i][j]));
    __syncthreads();

    if (tid < 128) {
        float h = 0.f, cgt = s_cgate[tid];
        for (int l = 0; l < NL; l++) {
            float x = s_X[l * NH + tid];
            float a = s_A[l * NH + tid];
            float m = s_mask[l];
            float hn = a * h + (1.f - a) * x;
            h = m * hn + (1.f - m) * h;
            s_X[l * NH + tid] = h * cgt;
        }
    }
    __syncthreads();

    if (tid < 32) {
        float p = 0.f;
        for (int j = tid; j < 128; j += 32) p += s_q[j] * s_attnW[128 + j];
        #pragma unroll
        for (int o = 16; o; o >>= 1) p += __shfl_xor_sync(~0u, p, o);
        if (tid == 0) s_qdot[0] = p + attn_b[0];
    }
    __syncthreads();
    {
        int w = tid >> 5, lane = tid & 31;
        for (int l = w; l < NL; l += 8) {
            float p = 0.f;
            #pragma unroll
            for (int j = lane; j < 128; j += 32) p += s_X[l * NH + j] * s_attnW[j];
            #pragma unroll
            for (int o = 16; o; o >>= 1) p += __shfl_xor_sync(~0u, p, o);
            if (lane == 0) {
                float sc = tanhf(p + s_qdot[0]);
                s_scores[l] = (s_mask[l] <= 0.f) ? -1e9f : sc;
            }
        }
    }
    __syncthreads();
    if (tid < 32) {
        float v0 = s_scores[tid], v1 = s_scores[tid + 32];
        float mx = fmaxf(v0, v1);
        #pragma unroll
        for (int o = 16; o; o >>= 1) mx = fmaxf(mx, __shfl_xor_sync(~0u, mx, o));
        float e0 = __expf(v0 - mx) * s_mask[tid];
        float e1 = __expf(v1 - mx) * s_mask[tid + 32];
        float s = e0 + e1;
        #pragma unroll
        for (int o = 16; o; o >>= 1) s += __shfl_xor_sync(~0u, s, o);
        s = fmaxf(s, 1e-9f);
        s_attn[tid] = e0 / s;
        s_attn[tid + 32] = e1 / s;
    }
    __syncthreads();
    if (tid < 128) {
        float c = 0.f;
        #pragma unroll 4
        for (int l = 0; l < NL; l++) c += s_X[l * NH + tid] * s_attn[l];
        float P = (s_q[tid] + c) * s_rel[tid];
        g_Ph[b * NH + tid] = __float2half_rn(P);
    }
}

// ---------------- score: persistent fp16 1-term mma.sync GEMM --------------
// D = fp16(P) * fp16(E)^T. Per-element rounding ~2^-11 each side ->
// output norm rel err ~3e-4 (3.4x under 1e-3).
// 148 persistent CTAs, 512 threads. A resident; B 3-stage cp.async pipeline.
#define ALD 136                 // A smem row stride (fp16), 272B
#define SLD 72                  // B smem row stride per k-chunk (fp16), 144B
#define SA_H 0
#define SB   34816
#define BSTAGE 36864
#define NSTAGES 3
#define SCORE_SMEM (SB + NSTAGES * BSTAGE)   // 145408
#define NTILES ((NENT + 255) / 256)          // 782

#define MMA_F16(d, a, b) asm volatile( \
    "mma.sync.aligned.m16n8k16.row.col.f32.f16.f16.f32 " \
    "{%0,%1,%2,%3},{%4,%5,%6,%7},{%8,%9},{%0,%1,%2,%3};" \
    : "+f"(d[0]), "+f"(d[1]), "+f"(d[2]), "+f"(d[3]) \
    : "r"(a[0]), "r"(a[1]), "r"(a[2]), "r"(a[3]), "r"(b[0]), "r"(b[1]))

#define LDSM_X4(r, addr) asm volatile( \
    "ldmatrix.sync.aligned.m8n8.x4.shared.b16 {%0,%1,%2,%3}, [%4];" \
    : "=r"((r)[0]), "=r"((r)[1]), "=r"((r)[2]), "=r"((r)[3]) : "r"(addr))

#define CP_ASYNC16(dst, src, srcsz) asm volatile( \
    "cp.async.cg.shared.global [%0], [%1], 16, %2;" \
    :: "r"(dst), "l"(src), "r"(srcsz) : "memory")

__device__ __forceinline__ uint32_t smem_u32(const void* p) {
    return (uint32_t)__cvta_generic_to_shared(p);
}

__global__ __launch_bounds__(512, 1) void score_kernel(float* __restrict__ out) {
    extern __shared__ char smem[];
    uint32_t sbase = smem_u32(smem);
    int tid = threadIdx.x, warp = tid >> 5, lane = tid & 31;
    int m0 = (blockIdx.x & 3) * 128;
    int nstart = blockIdx.x >> 2;                 // 0..36
    const int nstride = 37;

    int wm = (warp >> 3) * 64;                    // 2 warps in m
    int wn = (warp & 7) * 32;                     // 8 warps in n
    int aRow = lane & 15, aCol = (lane >> 4) * 8; // ldmatrix A
    int bRow = ((lane >> 4) << 3) + (lane & 7);   // ldmatrix B
    int bCol = ((lane >> 3) & 1) * 8;
    int arow = lane >> 2, acol = (lane & 3) * 2;  // accum layout

    // ---- A resident fill: 128 rows x 128 fp16 ----
    #pragma unroll
    for (int i = 0; i < 4; i++) {
        int idx = tid + i * 512;                  // 0..2047
        int r = idx >> 4, c = (idx & 15) * 8;
        *(uint4*)(smem + SA_H + r * (ALD * 2) + c * 2) =
            *(const uint4*)(g_Ph + (size_t)(m0 + r) * NH + c);
    }

    int ntiles = 0;
    for (int t = nstart; t < NTILES; t += nstride) ntiles++;
    int steps = ntiles * 2;                       // two 64-k-chunks per tile
    if (steps == 0) return;

    auto fillB = [&](int s) {
        int stage = s % NSTAGES;
        int n0 = (nstart + (s >> 1) * nstride) * 256;
        int kc = (s & 1) * 64;
        uint32_t bh = sbase + SB + stage * BSTAGE;
        #pragma unroll
        for (int i = 0; i < 4; i++) {
            int idx = tid + i * 512;              // 0..2047
            int r = idx >> 3;                     // 0..255
            int c = (idx & 7) * 8;                // 0..56
            int er = n0 + r;
            uint32_t srcsz = (er < NENT) ? 16u : 0u;
            size_t go = (size_t)er * NH + kc + c;
            uint32_t so = (uint32_t)(r * (SLD * 2) + c * 2);
            CP_ASYNC16(bh + so, g_Eh + (srcsz ? go : 0), srcsz);
        }
    };

    fillB(0);
    asm volatile("cp.async.commit_group;" ::: "memory");
    if (steps > 1) {
        fillB(1);
        asm volatile("cp.async.commit_group;" ::: "memory");
    }

    float acc[4][4][4];
    #pragma unroll
    for (int i = 0; i < 4; i++)
        #pragma unroll
        for (int j = 0; j < 4; j++)
            { acc[i][j][0]=0.f; acc[i][j][1]=0.f; acc[i][j][2]=0.f; acc[i][j][3]=0.f; }

    for (int s = 0; s < steps; s++) {
        if (s + 1 < steps)
            asm volatile("cp.async.wait_group 1;" ::: "memory");
        else
            asm volatile("cp.async.wait_group 0;" ::: "memory");
        __syncthreads();

        if (s + 2 < steps) {
            fillB(s + 2);
            asm volatile("cp.async.commit_group;" ::: "memory");
        }

        int stage = s % NSTAGES;
        int kA = (s & 1) * 64;
        const char* bhp = smem + SB + stage * BSTAGE;

        #pragma unroll
        for (int ks = 0; ks < 4; ks++) {
            int k = ks * 16;
            uint32_t aH[4][4], bH[2][4];
            #pragma unroll
            for (int mt = 0; mt < 4; mt++)
                LDSM_X4(aH[mt], sbase + SA_H +
                        (wm + mt * 16 + aRow) * (ALD * 2) + (kA + k + aCol) * 2);
            #pragma unroll
            for (int p = 0; p < 2; p++)
                LDSM_X4(bH[p], smem_u32(bhp + (wn + p * 16 + bRow) * (SLD * 2) + (k + bCol) * 2));
            #pragma unroll
            for (int mt = 0; mt < 4; mt++)
                #pragma unroll
                for (int nt = 0; nt < 4; nt++)
                    MMA_F16(acc[mt][nt], aH[mt], (&bH[nt >> 1][(nt & 1) * 2]));
        }

        if (s & 1) {
            int n0 = (nstart + (s >> 1) * nstride) * 256;
            #pragma unroll
            for (int mt = 0; mt < 4; mt++) {
                int row = m0 + wm + mt * 16 + arow;
                #pragma unroll
                for (int nt = 0; nt < 4; nt++) {
                    int col = n0 + wn + nt * 8 + acol;
                    if (col < NENT) {
                        __stcs((float2*)(out + (size_t)row * NENT + col),
                               make_float2(acc[mt][nt][0], acc[mt][nt][1]));
                        __stcs((float2*)(out + (size_t)(row + 8) * NENT + col),
                               make_float2(acc[mt][nt][2], acc[mt][nt][3]));
                    }
                }
            }
            #pragma unroll
            for (int i = 0; i < 4; i++)
                #pragma unroll
                for (int j = 0; j < 4; j++)
                    { acc[i][j][0]=0.f; acc[i][j][1]=0.f; acc[i][j][2]=0.f; acc[i][j][3]=0.f; }
        }
    }
}

// ---------------- launch ----------------------------------------------------
extern "C" void kernel_launch(void* const* d_in, const int* in_sizes, int n_in,
                              void* d_out, int out_size) {
    const int*   heads        = (const int*)d_in[0];
    const int*   relations    = (const int*)d_in[1];
    const int*   times        = (const int*)d_in[2];
    const int*   hist_ent     = (const int*)d_in[3];
    const int*   hist_rel     = (const int*)d_in[4];
    const float* hist_delta   = (const float*)d_in[5];
    const float* hist_mask    = (const float*)d_in[6];
    const float* entity_emb   = (const float*)d_in[7];
    const float* relation_emb = (const float*)d_in[8];
    const float* time_emb     = (const float*)d_in[9];
    const float* delta_W      = (const float*)d_in[10];
    const float* delta_b      = (const float*)d_in[11];
    const float* query_W      = (const float*)d_in[12];
    const float* query_b      = (const float*)d_in[13];
    const float* in_W         = (const float*)d_in[14];
    const float* in_b         = (const float*)d_in[15];
    const float* a_W          = (const float*)d_in[16];
    const float* a_b          = (const float*)d_in[17];
    const float* hyper_in_W   = (const float*)d_in[18];
    const float* hyper_in_b   = (const float*)d_in[19];
    const float* hyper_gate_W = (const float*)d_in[20];
    const float* hyper_gate_b = (const float*)d_in[21];
    const float* attn_W       = (const float*)d_in[22];
    const float* attn_b       = (const float*)d_in[23];
    float* out = (float*)d_out;

    cudaFuncSetAttribute(front_kernel, cudaFuncAttributeMaxDynamicSharedMemorySize, FRONT_SMEM);
    cudaFuncSetAttribute(score_kernel, cudaFuncAttributeMaxDynamicSharedMemorySize, SCORE_SMEM);

    convertE_kernel<<<(NENT * NH / 4) / 256, 256>>>(entity_emb);
    prep_kernel<<<NREL + 2, 128>>>(relation_emb, in_W, delta_W, delta_b);
    front_kernel<<<NB, 256, FRONT_SMEM>>>(
        heads, relations, times, hist_ent, hist_rel, hist_delta, hist_mask,
        entity_emb, relation_emb, time_emb, query_W, query_b, in_W, in_b,
        a_W, a_b, hyper_in_W, hyper_in_b, hyper_gate_W, hyper_gate_b,
        attn_W, attn_b);
    score_kernel<<<148, 512, SCORE_SMEM>>>(out);
}

// round 9
// speedup vs baseline: 1.7561x; 1.1774x over previous
#include <cuda_runtime.h>
#include <cuda_bf16.h>
#include <cuda_fp16.h>
#include <stdint.h>

#define NB   512
#define NL   64
#define NH   128
#define NENT 200000
#define NREL 500

// ---------------- scratch (__device__ globals; no allocs allowed) ----------
__device__ float g_Rproj[NREL * NH];        // relation_emb @ in_W[128:256]
__device__ float g_vdW[NH];                 // delta_W @ in_W[256:384]
__device__ float g_vdb[NH];                 // delta_b @ in_W[256:384]
__device__ __half g_Ph[NB * NH];            // (q+ctx)*rel, fp16
__device__ __half g_Eh[(size_t)NENT * NH];  // entity_emb rounded to fp16

// ---------------- shared macros ---------------------------------------------
#define MMA_F16(d, a, b) asm volatile( \
    "mma.sync.aligned.m16n8k16.row.col.f32.f16.f16.f32 " \
    "{%0,%1,%2,%3},{%4,%5,%6,%7},{%8,%9},{%0,%1,%2,%3};" \
    : "+f"(d[0]), "+f"(d[1]), "+f"(d[2]), "+f"(d[3]) \
    : "r"(a[0]), "r"(a[1]), "r"(a[2]), "r"(a[3]), "r"(b[0]), "r"(b[1]))

#define LDSM_X4(r, addr) asm volatile( \
    "ldmatrix.sync.aligned.m8n8.x4.shared.b16 {%0,%1,%2,%3}, [%4];" \
    : "=r"((r)[0]), "=r"((r)[1]), "=r"((r)[2]), "=r"((r)[3]) : "r"(addr))

#define LDSM_X4_T(r, addr) asm volatile( \
    "ldmatrix.sync.aligned.m8n8.x4.trans.shared.b16 {%0,%1,%2,%3}, [%4];" \
    : "=r"((r)[0]), "=r"((r)[1]), "=r"((r)[2]), "=r"((r)[3]) : "r"(addr))

#define CP_ASYNC16(dst, src, srcsz) asm volatile( \
    "cp.async.cg.shared.global [%0], [%1], 16, %2;" \
    :: "r"(dst), "l"(src), "r"(srcsz) : "memory")

__device__ __forceinline__ uint32_t smem_u32(const void* p) {
    return (uint32_t)__cvta_generic_to_shared(p);
}

// ---------------- convert entity table to fp16 ------------------------------
__global__ void convertE_kernel(const float* __restrict__ E) {
    int i = blockIdx.x * blockDim.x + threadIdx.x;      // one float4
    float4 v = ((const float4*)E)[i];
    ((__half2*)g_Eh)[2*i+0] = __floats2half2_rn(v.x, v.y);
    ((__half2*)g_Eh)[2*i+1] = __floats2half2_rn(v.z, v.w);
}

// ---------------- prep: fold relation/delta projections --------------------
__global__ void prep_kernel(const float* __restrict__ relation_emb,
                            const float* __restrict__ in_W,
                            const float* __restrict__ delta_W,
                            const float* __restrict__ delta_b) {
    int r = blockIdx.x, j = threadIdx.x;
    if (r < NREL) {
        __shared__ float sr[NH];
        sr[j] = relation_emb[r * NH + j];
        __syncthreads();
        float acc = 0.f;
        #pragma unroll 8
        for (int i = 0; i < NH; i++) acc += sr[i] * in_W[(NH + i) * NH + j];
        g_Rproj[r * NH + j] = acc;
    } else if (r == NREL) {
        float acc = 0.f;
        #pragma unroll 8
        for (int t = 0; t < 128; t++) acc += delta_W[t] * in_W[(256 + t) * NH + j];
        g_vdW[j] = acc;
    } else {
        float acc = 0.f;
        #pragma unroll 8
        for (int t = 0; t < 128; t++) acc += delta_b[t] * in_W[(256 + t) * NH + j];
        g_vdb[j] = acc;
    }
}

// ---------------- front: one CTA per batch row, tensor-core GEMMs ----------
// smem layout (bytes):
//  X fp32      @ 0       32768
//  A fp32      @ 32768   32768
//  NEh fp16    @ 65536   17408  (64 x 136)
//  NEl fp16    @ 82944   17408
//  W  fp16     @ 100352  34816  (128 x 136)
//  Xh fp16     @ 135168  17408
//  misc fp32   @ 152576  6656
#define F_LD 136
#define FRONT_SMEM 159232
__global__ __launch_bounds__(256) void front_kernel(
    const int* __restrict__ heads, const int* __restrict__ relations,
    const int* __restrict__ times, const int* __restrict__ hist_ent,
    const int* __restrict__ hist_rel, const float* __restrict__ hist_delta,
    const float* __restrict__ hist_mask, const float* __restrict__ entity_emb,
    const float* __restrict__ relation_emb, const float* __restrict__ time_emb,
    const float* __restrict__ query_W, const float* __restrict__ query_b,
    const float* __restrict__ in_W, const float* __restrict__ in_b,
    const float* __restrict__ a_W, const float* __restrict__ a_b,
    const float* __restrict__ hyper_in_W, const float* __restrict__ hyper_in_b,
    const float* __restrict__ hyper_gate_W, const float* __restrict__ hyper_gate_b,
    const float* __restrict__ attn_W, const float* __restrict__ attn_b)
{
    extern __shared__ char fsm[];
    float*  s_X   = (float*)fsm;
    float*  s_A   = (float*)(fsm + 32768);
    __half* s_NEh = (__half*)(fsm + 65536);
    __half* s_NEl = (__half*)(fsm + 82944);
    __half* s_W   = (__half*)(fsm + 100352);
    __half* s_Xh  = (__half*)(fsm + 135168);
    float*  s_misc = (float*)(fsm + 152576);
    float* s_rel    = s_misc;
    float* s_q      = s_misc + 128;
    float* s_cgate  = s_misc + 256;
    float* s_bias   = s_misc + 384;
    float* s_vdW    = s_misc + 512;
    float* s_attnW  = s_misc + 640;      // 256
    float* s_head   = s_misc + 896;
    float* s_tf     = s_misc + 1024;
    float* s_scores = s_misc + 1152;
    float* s_attn   = s_misc + 1216;
    float* s_delta  = s_misc + 1280;
    float* s_mask   = s_misc + 1344;
    int*   s_hr     = (int*)(s_misc + 1408);
    float* s_qdot   = s_misc + 1472;
    float* s_ab     = s_misc + 1480;     // 128

    int b = blockIdx.x, tid = threadIdx.x;
    int warp = tid >> 5, lane = tid & 31;

    // ---- phase 0 ----
    if (tid < 128) {
        s_head[tid] = entity_emb[(size_t)heads[b] * NH + tid];
        s_rel[tid]  = relation_emb[relations[b] * NH + tid];
        s_tf[tid]   = time_emb[times[b] * NH + tid];
        s_vdW[tid]  = g_vdW[tid];
        s_ab[tid]   = a_b[tid];
    } else {
        int j = tid - 128;
        s_attnW[j]       = attn_W[j];
        s_attnW[128 + j] = attn_W[128 + j];
    }
    if (tid < 64) {
        s_delta[tid] = hist_delta[b * NL + tid];
        s_mask[tid]  = hist_mask[b * NL + tid];
        s_hr[tid]    = hist_rel[b * NL + tid];
    }
    __syncthreads();

    // ---- phase 1: q / cond (scalar, small) ----
    if (tid < 128) {
        int j = tid;
        float p0 = query_b[j], p1 = 0.f, p2 = 0.f, p3 = 0.f;
        #pragma unroll 4
        for (int i = 0; i < 128; i += 4) {
            p0 += s_head[i+0] * query_W[(i+0) * NH + j];
            p1 += s_head[i+1] * query_W[(i+1) * NH + j];
            p2 += s_head[i+2] * query_W[(i+2) * NH + j];
            p3 += s_head[i+3] * query_W[(i+3) * NH + j];
        }
        #pragma unroll 4
        for (int i = 0; i < 128; i += 4) {
            p0 += s_rel[i+0] * query_W[(128+i+0) * NH + j];
            p1 += s_rel[i+1] * query_W[(128+i+1) * NH + j];
            p2 += s_rel[i+2] * query_W[(128+i+2) * NH + j];
            p3 += s_rel[i+3] * query_W[(128+i+3) * NH + j];
        }
        #pragma unroll 4
        for (int i = 0; i < 128; i += 4) {
            p0 += s_tf[i+0] * query_W[(256+i+0) * NH + j];
            p1 += s_tf[i+1] * query_W[(256+i+1) * NH + j];
            p2 += s_tf[i+2] * query_W[(256+i+2) * NH + j];
            p3 += s_tf[i+3] * query_W[(256+i+3) * NH + j];
        }
        s_q[j] = (p0 + p1) + (p2 + p3);
    } else {
        int j = tid - 128;
        float c0 = hyper_in_b[j], c1 = 0.f;
        float g0 = hyper_gate_b[j], g1 = 0.f;
        #pragma unroll 4
        for (int i = 0; i < 128; i += 2) {
            float r0 = s_rel[i], r1 = s_rel[i+1];
            c0 += r0 * hyper_in_W[i * NH + j];
            c1 += r1 * hyper_in_W[(i+1) * NH + j];
            g0 += r0 * hyper_gate_W[i * NH + j];
            g1 += r1 * hyper_gate_W[(i+1) * NH + j];
        }
        s_cgate[j] = 1.f / (1.f + __expf(-(g0 + g1)));
        s_bias[j]  = in_b[j] + (c0 + c1) + g_vdb[j];
    }

    // ---- gather NE -> fp16 hi/lo smem ----
    for (int l = warp; l < NL; l += 8) {
        size_t e = (size_t)hist_ent[b * NL + l];
        float4 v = ((const float4*)(entity_emb + e * NH))[lane];
        __half2 h0 = __floats2half2_rn(v.x, v.y);
        __half2 h1 = __floats2half2_rn(v.z, v.w);
        __half2 l0 = __floats2half2_rn(v.x - __half2float(__low2half(h0)),
                                       v.y - __half2float(__high2half(h0)));
        __half2 l1 = __floats2half2_rn(v.z - __half2float(__low2half(h1)),
                                       v.w - __half2float(__high2half(h1)));
        ((__half2*)(s_NEh + l * F_LD))[lane * 2]     = h0;
        ((__half2*)(s_NEh + l * F_LD))[lane * 2 + 1] = h1;
        ((__half2*)(s_NEl + l * F_LD))[lane * 2]     = l0;
        ((__half2*)(s_NEl + l * F_LD))[lane * 2 + 1] = l1;
    }

    // ---- W1 = in_W[0:128][:] -> fp16 smem ----
    #pragma unroll
    for (int i = 0; i < 16; i++) {
        int idx = tid + i * 256;                // float4 index 0..4095
        int k = idx >> 5, n = (idx & 31) * 4;
        float4 v = ((const float4*)in_W)[idx];
        ((__half2*)(s_W + k * F_LD + n))[0] = __floats2half2_rn(v.x, v.y);
        ((__half2*)(s_W + k * F_LD + n))[1] = __floats2half2_rn(v.z, v.w);
    }
    __syncthreads();

    // ---- GEMM1: Xraw = NE @ W1 (2-term A split) ----
    int wm = (warp >> 2) * 32;                  // 2 warps in m (64 rows)
    int wn = (warp & 3) * 32;                   // 4 warps in n (128 cols)
    int aRow = lane & 15, aCol = (lane >> 4) * 8;
    {
        float facc[2][4][4];
        #pragma unroll
        for (int i = 0; i < 2; i++)
            #pragma unroll
            for (int j = 0; j < 4; j++)
                { facc[i][j][0]=0.f; facc[i][j][1]=0.f; facc[i][j][2]=0.f; facc[i][j][3]=0.f; }
        #pragma unroll
        for (int ks = 0; ks < 8; ks++) {
            int k = ks * 16;
            uint32_t aF[2][4], alF[2][4], bF[2][4];
            #pragma unroll
            for (int mt = 0; mt < 2; mt++) {
                LDSM_X4(aF[mt],  smem_u32(s_NEh + (wm + mt*16 + aRow) * F_LD + k + aCol));
                LDSM_X4(alF[mt], smem_u32(s_NEl + (wm + mt*16 + aRow) * F_LD + k + aCol));
            }
            #pragma unroll
            for (int g = 0; g < 2; g++)
                LDSM_X4_T(bF[g], smem_u32(s_W + (k + aRow) * F_LD + wn + g*16 + aCol));
            #pragma unroll
            for (int mt = 0; mt < 2; mt++)
                #pragma unroll
                for (int j = 0; j < 4; j++)
                    MMA_F16(facc[mt][j], aF[mt], (&bF[j >> 1][(j & 1) * 2]));
            #pragma unroll
            for (int mt = 0; mt < 2; mt++)
                #pragma unroll
                for (int j = 0; j < 4; j++)
                    MMA_F16(facc[mt][j], alF[mt], (&bF[j >> 1][(j & 1) * 2]));
        }
        #pragma unroll
        for (int mt = 0; mt < 2; mt++) {
            int row = wm + mt * 16 + (lane >> 2);
            #pragma unroll
            for (int j = 0; j < 4; j++) {
                int col = wn + j * 8 + (lane & 3) * 2;
                *(float2*)(s_X + row * NH + col) = make_float2(facc[mt][j][0], facc[mt][j][1]);
                *(float2*)(s_X + (row + 8) * NH + col) = make_float2(facc[mt][j][2], facc[mt][j][3]);
            }
        }
    }
    __syncthreads();

    // ---- bias pass: X += bias + delta*vdW + Rproj[hr]; also Xh fp16 ----
    {
        int r0 = (tid >> 4) * 4, c0 = (tid & 15) * 8;
        #pragma unroll
        for (int i = 0; i < 4; i++) {
            int l = r0 + i;
            float dl = s_delta[l];
            const float* rp = g_Rproj + s_hr[l] * NH + c0;
            #pragma unroll
            for (int j = 0; j < 8; j++) {
                float x = s_X[l * NH + c0 + j] + s_bias[c0 + j] + dl * s_vdW[c0 + j] + rp[j];
                s_X[l * NH + c0 + j] = x;
                s_Xh[l * F_LD + c0 + j] = __float2half_rn(x);
            }
        }
    }
    __syncthreads();

    // ---- W2 = a_W -> fp16 smem ----
    #pragma unroll
    for (int i = 0; i < 16; i++) {
        int idx = tid + i * 256;
        int k = idx >> 5, n = (idx & 31) * 4;
        float4 v = ((const float4*)a_W)[idx];
        ((__half2*)(s_W + k * F_LD + n))[0] = __floats2half2_rn(v.x, v.y);
        ((__half2*)(s_W + k * F_LD + n))[1] = __floats2half2_rn(v.z, v.w);
    }
    __syncthreads();

    // ---- GEMM2: A = sigmoid(Xh @ W2 + a_b) ----
    {
        float facc[2][4][4];
        #pragma unroll
        for (int i = 0; i < 2; i++)
            #pragma unroll
            for (int j = 0; j < 4; j++)
                { facc[i][j][0]=0.f; facc[i][j][1]=0.f; facc[i][j][2]=0.f; facc[i][j][3]=0.f; }
        #pragma unroll
        for (int ks = 0; ks < 8; ks++) {
            int k = ks * 16;
            uint32_t aF[2][4], bF[2][4];
            #pragma unroll
            for (int mt = 0; mt < 2; mt++)
                LDSM_X4(aF[mt], smem_u32(s_Xh + (wm + mt*16 + aRow) * F_LD + k + aCol));
            #pragma unroll
            for (int g = 0; g < 2; g++)
                LDSM_X4_T(bF[g], smem_u32(s_W + (k + aRow) * F_LD + wn + g*16 + aCol));
            #pragma unroll
            for (int mt = 0; mt < 2; mt++)
                #pragma unroll
                for (int j = 0; j < 4; j++)
                    MMA_F16(facc[mt][j], aF[mt], (&bF[j >> 1][(j & 1) * 2]));
        }
        #pragma unroll
        for (int mt = 0; mt < 2; mt++) {
            int row = wm + mt * 16 + (lane >> 2);
            #pragma unroll
            for (int j = 0; j < 4; j++) {
                int col = wn + j * 8 + (lane & 3) * 2;
                float v0 = 1.f / (1.f + __expf(-(facc[mt][j][0] + s_ab[col])));
                float v1 = 1.f / (1.f + __expf(-(facc[mt][j][1] + s_ab[col + 1])));
                float v2 = 1.f / (1.f + __expf(-(facc[mt][j][2] + s_ab[col])));
                float v3 = 1.f / (1.f + __expf(-(facc[mt][j][3] + s_ab[col + 1])));
                *(float2*)(s_A + row * NH + col) = make_float2(v0, v1);
                *(float2*)(s_A + (row + 8) * NH + col) = make_float2(v2, v3);
            }
        }
    }
    __syncthreads();

    // ---- gated scan (history_seq overwrites s_X) ----
    if (tid < 128) {
        float h = 0.f, cgt = s_cgate[tid];
        for (int l = 0; l < NL; l++) {
            float x = s_X[l * NH + tid];
            float a = s_A[l * NH + tid];
            float m = s_mask[l];
            float hn = a * h + (1.f - a) * x;
            h = m * hn + (1.f - m) * h;
            s_X[l * NH + tid] = h * cgt;
        }
    }
    __syncthreads();

    // ---- attention ----
    if (tid < 32) {
        float p = 0.f;
        for (int j = tid; j < 128; j += 32) p += s_q[j] * s_attnW[128 + j];
        #pragma unroll
        for (int o = 16; o; o >>= 1) p += __shfl_xor_sync(~0u, p, o);
        if (tid == 0) s_qdot[0] = p + attn_b[0];
    }
    __syncthreads();
    for (int l = warp; l < NL; l += 8) {
        float p = 0.f;
        #pragma unroll
        for (int j = lane; j < 128; j += 32) p += s_X[l * NH + j] * s_attnW[j];
        #pragma unroll
        for (int o = 16; o; o >>= 1) p += __shfl_xor_sync(~0u, p, o);
        if (lane == 0) {
            float sc = tanhf(p + s_qdot[0]);
            s_scores[l] = (s_mask[l] <= 0.f) ? -1e9f : sc;
        }
    }
    __syncthreads();
    if (tid < 32) {
        float v0 = s_scores[tid], v1 = s_scores[tid + 32];
        float mx = fmaxf(v0, v1);
        #pragma unroll
        for (int o = 16; o; o >>= 1) mx = fmaxf(mx, __shfl_xor_sync(~0u, mx, o));
        float e0 = __expf(v0 - mx) * s_mask[tid];
        float e1 = __expf(v1 - mx) * s_mask[tid + 32];
        float s = e0 + e1;
        #pragma unroll
        for (int o = 16; o; o >>= 1) s += __shfl_xor_sync(~0u, s, o);
        s = fmaxf(s, 1e-9f);
        s_attn[tid] = e0 / s;
        s_attn[tid + 32] = e1 / s;
    }
    __syncthreads();
    if (tid < 128) {
        float c = 0.f;
        #pragma unroll 4
        for (int l = 0; l < NL; l++) c += s_X[l * NH + tid] * s_attn[l];
        float P = (s_q[tid] + c) * s_rel[tid];
        g_Ph[b * NH + tid] = __float2half_rn(P);
    }
}

// ---------------- score: persistent fp16 GEMM, 2 CTAs/SM -------------------
// CTA: 256 threads, tile 128m x 128n, K=128 resident A, 4-stage cp.async B.
#define ALD 136                 // A smem row stride (fp16)
#define SLD 72                  // B smem row stride per k-chunk (fp16)
#define SB_OFF 34816
#define BSTAGE 18432            // 128 x 72 x 2
#define NSTAGES 4
#define SCORE_SMEM (SB_OFF + NSTAGES * BSTAGE)   // 108544
#define NT128 ((NENT + 127) / 128)               // 1563
#define NSTRIDE 74

__global__ __launch_bounds__(256, 2) void score_kernel(float* __restrict__ out) {
    extern __shared__ char smem[];
    uint32_t sbase = smem_u32(smem);
    int tid = threadIdx.x, warp = tid >> 5, lane = tid & 31;
    int m0 = (blockIdx.x & 3) * 128;
    int nstart = blockIdx.x >> 2;                 // 0..73

    int wm = (warp >> 2) * 64;                    // 2 warps in m
    int wn = (warp & 3) * 32;                     // 4 warps in n
    int aRow = lane & 15, aCol = (lane >> 4) * 8;
    int bRow = ((lane >> 4) << 3) + (lane & 7);
    int bCol = ((lane >> 3) & 1) * 8;
    int arow = lane >> 2, acol = (lane & 3) * 2;

    // ---- A resident fill: 128 rows x 128 fp16 ----
    #pragma unroll
    for (int i = 0; i < 8; i++) {
        int idx = tid + i * 256;                  // 0..2047
        int r = idx >> 4, c = (idx & 15) * 8;
        *(uint4*)(smem + r * (ALD * 2) + c * 2) =
            *(const uint4*)(g_Ph + (size_t)(m0 + r) * NH + c);
    }

    int ntiles = 0;
    for (int t = nstart; t < NT128; t += NSTRIDE) ntiles++;
    int steps = ntiles * 2;
    if (steps == 0) return;

    auto fillB = [&](int s) {
        int stage = s & 3;
        int n0 = (nstart + (s >> 1) * NSTRIDE) * 128;
        int kc = (s & 1) * 64;
        uint32_t bh = sbase + SB_OFF + stage * BSTAGE;
        #pragma unroll
        for (int i = 0; i < 4; i++) {
            int idx = tid + i * 256;              // 0..1023
            int r = idx >> 3;                     // 0..127
            int c = (idx & 7) * 8;
            int er = n0 + r;
            uint32_t srcsz = (er < NENT) ? 16u : 0u;
            size_t go = (size_t)er * NH + kc + c;
            uint32_t so = (uint32_t)(r * (SLD * 2) + c * 2);
            CP_ASYNC16(bh + so, g_Eh + (srcsz ? go : 0), srcsz);
        }
    };

    // prefill 3 stages
    fillB(0); asm volatile("cp.async.commit_group;" ::: "memory");
    if (steps > 1) { fillB(1); asm volatile("cp.async.commit_group;" ::: "memory"); }
    if (steps > 2) { fillB(2); asm volatile("cp.async.commit_group;" ::: "memory"); }

    float acc[4][4][4];
    #pragma unroll
    for (int i = 0; i < 4; i++)
        #pragma unroll
        for (int j = 0; j < 4; j++)
            { acc[i][j][0]=0.f; acc[i][j][1]=0.f; acc[i][j][2]=0.f; acc[i][j][3]=0.f; }

    for (int s = 0; s < steps; s++) {
        int rem = steps - 1 - s;
        if (rem >= 2)      asm volatile("cp.async.wait_group 2;" ::: "memory");
        else if (rem == 1) asm volatile("cp.async.wait_group 1;" ::: "memory");
        else               asm volatile("cp.async.wait_group 0;" ::: "memory");
        __syncthreads();

        if (s + 3 < steps) {
            fillB(s + 3);
            asm volatile("cp.async.commit_group;" ::: "memory");
        }

        int stage = s & 3;
        int kA = (s & 1) * 64;
        const char* bhp = smem + SB_OFF + stage * BSTAGE;

        #pragma unroll
        for (int ks = 0; ks < 4; ks++) {
            int k = ks * 16;
            uint32_t aH[4][4], bH[2][4];
            #pragma unroll
            for (int mt = 0; mt < 4; mt++)
                LDSM_X4(aH[mt], sbase +
                        (wm + mt * 16 + aRow) * (ALD * 2) + (kA + k + aCol) * 2);
            #pragma unroll
            for (int p = 0; p < 2; p++)
                LDSM_X4(bH[p], smem_u32(bhp + (wn + p * 16 + bRow) * (SLD * 2) + (k + bCol) * 2));
            #pragma unroll
            for (int mt = 0; mt < 4; mt++)
                #pragma unroll
                for (int nt = 0; nt < 4; nt++)
                    MMA_F16(acc[mt][nt], aH[mt], (&bH[nt >> 1][(nt & 1) * 2]));
        }

        if (s & 1) {
            int n0 = (nstart + (s >> 1) * NSTRIDE) * 128;
            #pragma unroll
            for (int mt = 0; mt < 4; mt++) {
                int row = m0 + wm + mt * 16 + arow;
                #pragma unroll
                for (int nt = 0; nt < 4; nt++) {
                    int col = n0 + wn + nt * 8 + acol;
                    if (col < NENT) {
                        __stcs((float2*)(out + (size_t)row * NENT + col),
                               make_float2(acc[mt][nt][0], acc[mt][nt][1]));
                        __stcs((float2*)(out + (size_t)(row + 8) * NENT + col),
                               make_float2(acc[mt][nt][2], acc[mt][nt][3]));
                    }
                }
            }
            #pragma unroll
            for (int i = 0; i < 4; i++)
                #pragma unroll
                for (int j = 0; j < 4; j++)
                    { acc[i][j][0]=0.f; acc[i][j][1]=0.f; acc[i][j][2]=0.f; acc[i][j][3]=0.f; }
        }
    }
}

// ---------------- launch ----------------------------------------------------
extern "C" void kernel_launch(void* const* d_in, const int* in_sizes, int n_in,
                              void* d_out, int out_size) {
    const int*   heads        = (const int*)d_in[0];
    const int*   relations    = (const int*)d_in[1];
    const int*   times        = (const int*)d_in[2];
    const int*   hist_ent     = (const int*)d_in[3];
    const int*   hist_rel     = (const int*)d_in[4];
    const float* hist_delta   = (const float*)d_in[5];
    const float* hist_mask    = (const float*)d_in[6];
    const float* entity_emb   = (const float*)d_in[7];
    const float* relation_emb = (const float*)d_in[8];
    const float* time_emb     = (const float*)d_in[9];
    const float* delta_W      = (const float*)d_in[10];
    const float* delta_b      = (const float*)d_in[11];
    const float* query_W      = (const float*)d_in[12];
    const float* query_b      = (const float*)d_in[13];
    const float* in_W         = (const float*)d_in[14];
    const float* in_b         = (const float*)d_in[15];
    const float* a_W          = (const float*)d_in[16];
    const float* a_b          = (const float*)d_in[17];
    const float* hyper_in_W   = (const float*)d_in[18];
    const float* hyper_in_b   = (const float*)d_in[19];
    const float* hyper_gate_W = (const float*)d_in[20];
    const float* hyper_gate_b = (const float*)d_in[21];
    const float* attn_W       = (const float*)d_in[22];
    const float* attn_b       = (const float*)d_in[23];
    float* out = (float*)d_out;

    cudaFuncSetAttribute(front_kernel, cudaFuncAttributeMaxDynamicSharedMemorySize, FRONT_SMEM);
    cudaFuncSetAttribute(score_kernel, cudaFuncAttributeMaxDynamicSharedMemorySize, SCORE_SMEM);

    convertE_kernel<<<(NENT * NH / 4) / 256, 256>>>(entity_emb);
    prep_kernel<<<NREL + 2, 128>>>(relation_emb, in_W, delta_W, delta_b);
    front_kernel<<<NB, 256, FRONT_SMEM>>>(
        heads, relations, times, hist_ent, hist_rel, hist_delta, hist_mask,
        entity_emb, relation_emb, time_emb, query_W, query_b, in_W, in_b,
        a_W, a_b, hyper_in_W, hyper_in_b, hyper_gate_W, hyper_gate_b,
        attn_W, attn_b);
    score_kernel<<<296, 256, SCORE_SMEM>>>(out);
}